// round 2
// baseline (speedup 1.0000x reference)
#include <cuda_runtime.h>
#include <math.h>

#define KKEY   2048
#define CFEAT  128
#define M_GRID 216
#define NPROP  48
#define NPTS   (NPROP*M_GRID)      // 10368 per batch
#define NTOT   (2*NPTS)            // 20736
#define QDIM   (128*M_GRID)        // 27648
#define KSPLIT 27
#define KCHUNK 1024

typedef unsigned long long ull;

// ---------------- f32x2 helpers (packed fp32, sm_10x) ----------------
__device__ __forceinline__ ull pack2(float lo, float hi) {
    ull r;
    asm("mov.b64 %0, {%1, %2};" : "=l"(r) : "f"(lo), "f"(hi));
    return r;
}
__device__ __forceinline__ ull ffma2(ull a, ull b, ull c) {
    ull d;
    asm("fma.rn.f32x2 %0, %1, %2, %3;" : "=l"(d) : "l"(a), "l"(b), "l"(c));
    return d;
}
__device__ __forceinline__ float2 unpack2(ull v) {
    float2 f;
    asm("mov.b64 {%0, %1}, %2;" : "=f"(f.x), "=f"(f.y) : "l"(v));
    return f;
}

// ---------------- scratch ----------------
__device__ float g_new_xyz[NTOT*3];
__device__ float g_pre[2*2*KKEY*64];          // [scale][b][k][interleaved o]
__device__ float g_pooled[2*NPROP*QDIM];      // 96 x 27648, q = co*216+mm
__device__ float g_partial[KSPLIT*96*256];

// ---------------- kernel A: grid transform -> new_xyz ----------------
__global__ void __launch_bounds__(256) kA(const float* __restrict__ prop,
                                          const float* __restrict__ gnoise) {
    int t = blockIdx.x*256 + threadIdx.x;
    if (t >= NTOT) return;
    int b = t / NPTS, r = t % NPTS;
    int n = r / M_GRID, mm = r % M_GRID;
    const float* p = prop + (size_t)(b*NPROP + n)*7;
    const float* g = gnoise + ((size_t)(b*NPROP + n)*M_GRID + mm)*3;
    float gx = g[0]*p[3], gy = g[1]*p[4], gz = g[2]*p[5];
    float c = cosf(p[6]), s = sinf(p[6]);
    float* o = g_new_xyz + (size_t)t*3;
    o[0] = c*gx - s*gy + p[0];
    o[1] = s*gx + c*gy + p[1];
    o[2] = gz + p[2];
}

// ---------------- kernel B: pre[k][o] = W0[:,3:] . feats[:,k] ----------------
// Output layout interleaved: g_pre[...k<<6 + (o&31)*2 + (o>>5)] so kC can LDG.64
// the (lane, lane+32) pair. f32x2 packs adjacent k outputs.
__global__ void __launch_bounds__(256) kB(const float* __restrict__ feats,
                                          const float* __restrict__ w0,
                                          const float* __restrict__ w1) {
    __shared__ float Ws[CFEAT*64];   // [c][o]
    __shared__ float fs[CFEAT*32];   // [c][k-local]
    int sb = blockIdx.y; int sc = sb >> 1, b = sb & 1;
    const float* W = sc ? w1 : w0;
    for (int i = threadIdx.x; i < CFEAT*64; i += 256) {
        int c = i >> 6, o = i & 63;
        Ws[i] = W[o*131 + 3 + c];
    }
    int kbase = blockIdx.x * 32;
    const float* fb = feats + (size_t)b*CFEAT*KKEY + kbase;
    for (int i = threadIdx.x; i < CFEAT*8; i += 256) {
        int c = i >> 3, q = i & 7;
        *(float4*)(fs + c*32 + q*4) = *(const float4*)(fb + (size_t)c*KKEY + q*4);
    }
    __syncthreads();

    int o  = threadIdx.x & 63;
    int kk = threadIdx.x >> 6;          // 0..3, octet of 8 k
    ull acc0 = 0, acc1 = 0, acc2 = 0, acc3 = 0;
    #pragma unroll 4
    for (int c = 0; c < CFEAT; c++) {
        float w = Ws[c*64 + o];
        ull wd = pack2(w, w);
        const ull* f = (const ull*)(fs + c*32 + kk*8);
        acc0 = ffma2(wd, f[0], acc0);
        acc1 = ffma2(wd, f[1], acc1);
        acc2 = ffma2(wd, f[2], acc2);
        acc3 = ffma2(wd, f[3], acc3);
    }
    size_t base = ((size_t)(sc*2 + b)*KKEY + kbase + kk*8) << 6;
    int oi = ((o & 31) << 1) + (o >> 5);
    float2 u;
    u = unpack2(acc0); g_pre[base + oi] = u.x; g_pre[base + 64 + oi] = u.y;
    u = unpack2(acc1); g_pre[base + 128 + oi] = u.x; g_pre[base + 192 + oi] = u.y;
    u = unpack2(acc2); g_pre[base + 256 + oi] = u.x; g_pre[base + 320 + oi] = u.y;
    u = unpack2(acc3); g_pre[base + 384 + oi] = u.x; g_pre[base + 448 + oi] = u.y;
}

// ---------------- kernel C: ball query + 2-layer MLP + maxpool ----------------
// smem (floats):
//  kx[2048] ky[2048] kz[2048]                        0..6144
//  w1d[2][64][64] duplicated float2 pairs            6144..22528
//  wxyz[2][3][64]                                    22528..22912
//  b0s[2][64] b1s[2][64]                             22912..23168
//  h0b[8][64][4]  ([j][s])                           23168..25216
//  idx1[8][32] idx0[8][16] (ints)                    25216..25600
#define KC_SMEM_WORDS 25600
__global__ void __launch_bounds__(256) kC(
    const float* __restrict__ kxyzg,
    const float* __restrict__ w00, const float* __restrict__ b00,
    const float* __restrict__ w01, const float* __restrict__ b01,
    const float* __restrict__ w10, const float* __restrict__ b10,
    const float* __restrict__ w11, const float* __restrict__ b11)
{
    extern __shared__ float sm[];
    float* kxs  = sm;
    float* kys  = sm + 2048;
    float* kzs  = sm + 4096;
    float* w1d  = sm + 6144;
    float* wxyz = sm + 22528;
    float* b0s  = sm + 22912;
    float* b1s  = sm + 23040;
    float* h0b  = sm + 23168;
    int*   idx1 = (int*)(sm + 25216);
    int*   idx0 = (int*)(sm + 25472);

    const int b = blockIdx.x / 1296;

    const float* kb = kxyzg + (size_t)b*KKEY*3;
    for (int i = threadIdx.x; i < KKEY; i += 256) {
        kxs[i] = kb[i*3]; kys[i] = kb[i*3+1]; kzs[i] = kb[i*3+2];
    }
    for (int i = threadIdx.x; i < 2*4096; i += 256) {
        int sc = i >> 12, t = i & 4095, j = t >> 6, o = t & 63;
        float v = (sc ? w11 : w01)[o*64 + j];
        float2* dst = (float2*)w1d + (size_t)i;
        *dst = make_float2(v, v);
    }
    for (int i = threadIdx.x; i < 2*3*64; i += 256) {
        int sc = i / 192, t = i % 192, d = t / 64, o = t % 64;
        wxyz[i] = (sc ? w10 : w00)[o*131 + d];
    }
    if (threadIdx.x < 128) {
        int sc = threadIdx.x >> 6, o = threadIdx.x & 63;
        b0s[threadIdx.x] = (sc ? b10 : b00)[o];
        b1s[threadIdx.x] = (sc ? b11 : b01)[o];
    }
    __syncthreads();

    const int w = threadIdx.x >> 5, lane = threadIdx.x & 31;
    const int p  = blockIdx.x*8 + w;
    const int rp = p % NPTS;
    const float px = g_new_xyz[(size_t)p*3], py = g_new_xyz[(size_t)p*3+1],
                pz = g_new_xyz[(size_t)p*3+2];
    const float pn = fmaf(px,px, fmaf(py,py, pz*pz));

    // ---- ordered ball query ----
    const float R0 = 0.8f*0.8f, R1 = 1.6f*1.6f;
    int* l1 = idx1 + w*32;
    int* l0 = idx0 + w*16;
    int c0 = 0, c1 = 0;
    const unsigned lt = (1u << lane) - 1u;
    for (int base = 0; base < KKEY; base += 32) {
        int k = base + lane;
        float kx = kxs[k], ky = kys[k], kz = kzs[k];
        float kn  = fmaf(kx,kx, fmaf(ky,ky, kz*kz));
        float dot = fmaf(px,kx, fmaf(py,ky, pz*kz));
        float d2  = fmaf(-2.f, dot, pn + kn);
        bool v1 = d2 < R1, v0 = d2 < R0;
        unsigned m1 = __ballot_sync(0xffffffffu, v1);
        unsigned m0 = __ballot_sync(0xffffffffu, v0);
        if (c1 < 32 && m1) {
            if (v1) { int rk = c1 + __popc(m1 & lt); if (rk < 32) l1[rk] = k; }
            c1 = min(32, c1 + __popc(m1));
        }
        if (c0 < 16 && m0) {
            if (v0) { int rk = c0 + __popc(m0 & lt); if (rk < 16) l0[rk] = k; }
            c0 = min(16, c0 + __popc(m0));
        }
        if (c0 >= 16 && c1 >= 32) break;
    }
    __syncwarp();

    const int n  = rp / M_GRID, mm = rp % M_GRID;
    float* hb = h0b + w*256;

    #pragma unroll
    for (int sc = 0; sc < 2; sc++) {
        int cnt = sc ? c1 : c0;
        int* lst = sc ? l1 : l0;
        if (cnt == 0) { if (lane == 0) lst[0] = 0; cnt = 1; __syncwarp(); }

        const float* preb = g_pre + ((size_t)(sc*2 + b)*KKEY << 6);
        const ull* wt = (const ull*)((const float2*)w1d + sc*4096);
        const float* wx = wxyz + sc*192;
        const float bias0a = b0s[sc*64 + lane],  bias0b = b0s[sc*64 + lane + 32];
        const ull biasA2 = pack2(b1s[sc*64 + lane],      b1s[sc*64 + lane]);
        const ull biasB2 = pack2(b1s[sc*64 + lane + 32], b1s[sc*64 + lane + 32]);
        const float wxa0 = wx[lane],       wxa1 = wx[64+lane],      wxa2 = wx[128+lane];
        const float wxb0 = wx[lane+32],    wxb1 = wx[96+lane],      wxb2 = wx[160+lane];
        float mxa = 0.f, mxb = 0.f;

        for (int s0 = 0; s0 < cnt; s0 += 4) {
            float ha[4], hbv[4];
            #pragma unroll
            for (int s = 0; s < 4; s++) {
                int si = s0 + s;
                int k  = lst[si < cnt ? si : 0];
                float rx = kxs[k]-px, ry = kys[k]-py, rz = kzs[k]-pz;
                const float2 pr2 = *(const float2*)(preb + ((size_t)k << 6) + (lane << 1));
                float va = pr2.x + bias0a;
                va = fmaf(rx, wxa0, va);
                va = fmaf(ry, wxa1, va);
                va = fmaf(rz, wxa2, va);
                ha[s] = fmaxf(va, 0.f);
                float vb = pr2.y + bias0b;
                vb = fmaf(rx, wxb0, vb);
                vb = fmaf(ry, wxb1, vb);
                vb = fmaf(rz, wxb2, vb);
                hbv[s] = fmaxf(vb, 0.f);
            }
            *(float4*)(hb + (lane << 2))        = make_float4(ha[0],ha[1],ha[2],ha[3]);
            *(float4*)(hb + ((lane + 32) << 2)) = make_float4(hbv[0],hbv[1],hbv[2],hbv[3]);
            __syncwarp();

            ull a01 = biasA2, a23 = biasA2, e01 = biasB2, e23 = biasB2;
            #pragma unroll 16
            for (int j = 0; j < 64; j++) {
                ull wA2 = wt[j*64 + lane];
                ull wB2 = wt[j*64 + lane + 32];
                ulonglong2 hv = *(const ulonglong2*)(hb + (j << 2));
                a01 = ffma2(wA2, hv.x, a01);
                a23 = ffma2(wA2, hv.y, a23);
                e01 = ffma2(wB2, hv.x, e01);
                e23 = ffma2(wB2, hv.y, e23);
            }
            float2 fa = unpack2(a01), fb2 = unpack2(a23);
            float2 fe = unpack2(e01), ff = unpack2(e23);
            mxa = fmaxf(mxa, fmaxf(fmaxf(fa.x,fa.y), fmaxf(fb2.x,fb2.y)));
            mxb = fmaxf(mxb, fmaxf(fmaxf(fe.x,fe.y), fmaxf(ff.x,ff.y)));
            __syncwarp();
        }
        size_t row = (size_t)(b*NPROP + n);
        g_pooled[row*QDIM + (size_t)(sc*64 + lane)*M_GRID + mm]      = mxa;
        g_pooled[row*QDIM + (size_t)(sc*64 + lane + 32)*M_GRID + mm] = mxb;
    }
}

// ---------------- kernel D: K-split GEMM partial = pooled @ red_w0^T ----------------
// block tile 16 rows x 256 cols, thread tile 2 rows x 8 cols (4 f32x2 col-pairs)
#define XS_PITCH 18
#define WS_PITCH 258
__global__ void __launch_bounds__(256) kD(const float* __restrict__ w0) {
    __shared__ float xs[16*XS_PITCH];     // [kk][row]
    __shared__ float ws[16*WS_PITCH];     // [kk][col]
    const int tid = threadIdx.x;
    const int tc = tid & 31, tr = tid >> 5;      // col lane 0..31, row group 0..7
    const int rowbase = blockIdx.x * 16;
    const int kz = blockIdx.y;

    ull acc0[4] = {0,0,0,0};
    ull acc1[4] = {0,0,0,0};

    for (int kbb = 0; kbb < KCHUNK; kbb += 16) {
        int kg = kz*KCHUNK + kbb;
        {   // x tile: 16 rows x 16 k
            int row = tid >> 4, kk = tid & 15;
            xs[kk*XS_PITCH + row] = g_pooled[(size_t)(rowbase + row)*QDIM + kg + kk];
        }
        #pragma unroll
        for (int u = tid; u < 1024; u += 256) {   // w tile: 256 cols x 16 k (transpose)
            int col = u >> 2, k4 = (u & 3) << 2;
            float4 v = *(const float4*)(w0 + (size_t)col*QDIM + kg + k4);
            ws[(k4+0)*WS_PITCH + col] = v.x;
            ws[(k4+1)*WS_PITCH + col] = v.y;
            ws[(k4+2)*WS_PITCH + col] = v.z;
            ws[(k4+3)*WS_PITCH + col] = v.w;
        }
        __syncthreads();
        #pragma unroll
        for (int kk = 0; kk < 16; kk++) {
            float2 xr = *(const float2*)(xs + kk*XS_PITCH + tr*2);
            ull x0 = pack2(xr.x, xr.x);
            ull x1 = pack2(xr.y, xr.y);
            #pragma unroll
            for (int q = 0; q < 4; q++) {
                ull wv = *(const ull*)(ws + kk*WS_PITCH + (q << 6) + (tc << 1));
                acc0[q] = ffma2(x0, wv, acc0[q]);
                acc1[q] = ffma2(x1, wv, acc1[q]);
            }
        }
        __syncthreads();
    }
    #pragma unroll
    for (int q = 0; q < 4; q++) {
        int col = (q << 6) + (tc << 1);
        int row0 = rowbase + tr*2;
        *(float2*)(g_partial + ((size_t)kz*96 + row0)*256 + col)     = unpack2(acc0[q]);
        *(float2*)(g_partial + ((size_t)kz*96 + row0 + 1)*256 + col) = unpack2(acc1[q]);
    }
}

// ---------------- kernel E: reduce + relu + 256x256 GEMM + relu ----------------
__global__ void __launch_bounds__(256) kE(const float* __restrict__ rb0,
                                          const float* __restrict__ rw1,
                                          const float* __restrict__ rb1,
                                          float* __restrict__ out) {
    __shared__ float h2s[256];
    __shared__ float w1s[256*33];
    const int row = blockIdx.x;
    const int o = threadIdx.x;
    float s = rb0[o];
    #pragma unroll
    for (int ks = 0; ks < KSPLIT; ks++)
        s += g_partial[((size_t)ks*96 + row)*256 + o];
    h2s[o] = fmaxf(s, 0.f);
    __syncthreads();

    float acc = rb1[o];
    for (int jt = 0; jt < 256; jt += 32) {
        for (int i = threadIdx.x; i < 8192; i += 256) {
            int oo = i >> 5, jj = i & 31;
            w1s[oo*33 + jj] = rw1[(size_t)oo*256 + jt + jj];
        }
        __syncthreads();
        #pragma unroll
        for (int jj = 0; jj < 32; jj++)
            acc = fmaf(h2s[jt + jj], w1s[o*33 + jj], acc);
        __syncthreads();
    }
    out[(size_t)row*256 + o] = fmaxf(acc, 0.f);
}

// ---------------- launch ----------------
extern "C" void kernel_launch(void* const* d_in, const int* in_sizes, int n_in,
                              void* d_out, int out_size) {
    const float* proposals = (const float*)d_in[0];
    const float* kxyz      = (const float*)d_in[1];
    const float* kfeat     = (const float*)d_in[2];
    const float* gnoise    = (const float*)d_in[3];
    const float* w00 = (const float*)d_in[4];
    const float* b00 = (const float*)d_in[5];
    const float* w01 = (const float*)d_in[6];
    const float* b01 = (const float*)d_in[7];
    const float* w10 = (const float*)d_in[8];
    const float* b10 = (const float*)d_in[9];
    const float* w11 = (const float*)d_in[10];
    const float* b11 = (const float*)d_in[11];
    const float* rw0 = (const float*)d_in[12];
    const float* rb0 = (const float*)d_in[13];
    const float* rw1 = (const float*)d_in[14];
    const float* rb1 = (const float*)d_in[15];
    float* out = (float*)d_out;

    cudaFuncSetAttribute(kC, cudaFuncAttributeMaxDynamicSharedMemorySize,
                         KC_SMEM_WORDS * 4);

    kA<<<(NTOT + 255)/256, 256>>>(proposals, gnoise);
    kB<<<dim3(KKEY/32, 4), 256>>>(kfeat, w00, w10);
    kC<<<NTOT/8, 256, KC_SMEM_WORDS * 4>>>(kxyz, w00, b00, w01, b01,
                                           w10, b10, w11, b11);
    kD<<<dim3(6, KSPLIT), 256>>>(rw0);
    kE<<<96, 256>>>(rb0, rw1, rb1, out);
}

// round 3
// speedup vs baseline: 1.3331x; 1.3331x over previous
#include <cuda_runtime.h>
#include <math.h>

#define KKEY   2048
#define CFEAT  128
#define M_GRID 216
#define NPROP  48
#define NPTS   (NPROP*M_GRID)      // 10368 per batch
#define NTOT   (2*NPTS)            // 20736
#define QDIM   (128*M_GRID)        // 27648
#define KSPLIT 54
#define KCHUNK 512

typedef unsigned long long ull;

// f32x2 kept ONLY in kB (tiny kernel, already validated numerically)
__device__ __forceinline__ ull pack2(float lo, float hi) {
    ull r; asm("mov.b64 %0, {%1, %2};" : "=l"(r) : "f"(lo), "f"(hi)); return r;
}
__device__ __forceinline__ ull ffma2(ull a, ull b, ull c) {
    ull d; asm("fma.rn.f32x2 %0, %1, %2, %3;" : "=l"(d) : "l"(a), "l"(b), "l"(c)); return d;
}
__device__ __forceinline__ float2 unpack2(ull v) {
    float2 f; asm("mov.b64 {%0, %1}, %2;" : "=f"(f.x), "=f"(f.y) : "l"(v)); return f;
}

// ---------------- scratch ----------------
__device__ float g_new_xyz[NTOT*3];
__device__ float g_pre[2*2*KKEY*64];          // [scale][b][k][interleaved o]
__device__ float g_pooled[2*NPROP*QDIM];      // 96 x 27648, q = co*216+mm
__device__ float g_partial[KSPLIT*96*256];

// ---------------- kernel A ----------------
__global__ void __launch_bounds__(256) kA(const float* __restrict__ prop,
                                          const float* __restrict__ gnoise) {
    int t = blockIdx.x*256 + threadIdx.x;
    if (t >= NTOT) return;
    int b = t / NPTS, r = t % NPTS;
    int n = r / M_GRID, mm = r % M_GRID;
    const float* p = prop + (size_t)(b*NPROP + n)*7;
    const float* g = gnoise + ((size_t)(b*NPROP + n)*M_GRID + mm)*3;
    float gx = g[0]*p[3], gy = g[1]*p[4], gz = g[2]*p[5];
    float c = cosf(p[6]), s = sinf(p[6]);
    float* o = g_new_xyz + (size_t)t*3;
    o[0] = c*gx - s*gy + p[0];
    o[1] = s*gx + c*gy + p[1];
    o[2] = gz + p[2];
}

// ---------------- kernel B: pre[k][o] = W0[:,3:] . feats[:,k] ----------------
// interleaved output: g_pre[... k<<6 + (o&31)*2 + (o>>5)]
__global__ void __launch_bounds__(256) kB(const float* __restrict__ feats,
                                          const float* __restrict__ w0,
                                          const float* __restrict__ w1) {
    __shared__ float Ws[CFEAT*64];   // [c][o]
    __shared__ float fs[CFEAT*32];   // [c][k-local]
    int sb = blockIdx.y; int sc = sb >> 1, b = sb & 1;
    const float* W = sc ? w1 : w0;
    for (int i = threadIdx.x; i < CFEAT*64; i += 256) {
        int c = i >> 6, o = i & 63;
        Ws[i] = W[o*131 + 3 + c];
    }
    int kbase = blockIdx.x * 32;
    const float* fb = feats + (size_t)b*CFEAT*KKEY + kbase;
    for (int i = threadIdx.x; i < CFEAT*8; i += 256) {
        int c = i >> 3, q = i & 7;
        *(float4*)(fs + c*32 + q*4) = *(const float4*)(fb + (size_t)c*KKEY + q*4);
    }
    __syncthreads();

    int o  = threadIdx.x & 63;
    int kk = threadIdx.x >> 6;
    ull acc0 = 0, acc1 = 0, acc2 = 0, acc3 = 0;
    #pragma unroll 4
    for (int c = 0; c < CFEAT; c++) {
        float w = Ws[c*64 + o];
        ull wd = pack2(w, w);
        const ull* f = (const ull*)(fs + c*32 + kk*8);
        acc0 = ffma2(wd, f[0], acc0);
        acc1 = ffma2(wd, f[1], acc1);
        acc2 = ffma2(wd, f[2], acc2);
        acc3 = ffma2(wd, f[3], acc3);
    }
    size_t base = ((size_t)(sc*2 + b)*KKEY + kbase + kk*8) << 6;
    int oi = ((o & 31) << 1) + (o >> 5);
    float2 u;
    u = unpack2(acc0); g_pre[base + oi] = u.x; g_pre[base + 64 + oi] = u.y;
    u = unpack2(acc1); g_pre[base + 128 + oi] = u.x; g_pre[base + 192 + oi] = u.y;
    u = unpack2(acc2); g_pre[base + 256 + oi] = u.x; g_pre[base + 320 + oi] = u.y;
    u = unpack2(acc3); g_pre[base + 384 + oi] = u.x; g_pre[base + 448 + oi] = u.y;
}

// ---------------- kernel C: ball query + 2-layer MLP + maxpool ----------------
// smem (floats):
//  kx[2048] ky[2048] kz[2048]                 0..6144
//  w1p[2][64][32] float2 pairs                6144..14336
//  wxyz[2][3][64]                             14336..14720
//  b0s[2][64] b1s[2][64]                      14720..14976
//  h0b[8][64][4]                              14976..17024
//  idx1[8][32] idx0[8][16] (ints)             17024..17408
#define KC_SMEM_WORDS 17408
__global__ void __launch_bounds__(256) kC(
    const float* __restrict__ kxyzg,
    const float* __restrict__ w00, const float* __restrict__ b00,
    const float* __restrict__ w01, const float* __restrict__ b01,
    const float* __restrict__ w10, const float* __restrict__ b10,
    const float* __restrict__ w11, const float* __restrict__ b11)
{
    extern __shared__ float sm[];
    float* kxs  = sm;
    float* kys  = sm + 2048;
    float* kzs  = sm + 4096;
    float2* w1p = (float2*)(sm + 6144);       // [sc][j][pr]
    float* wxyz = sm + 14336;
    float* b0s  = sm + 14720;
    float* b1s  = sm + 14848;
    float* h0b  = sm + 14976;
    int*   idx1 = (int*)(sm + 17024);
    int*   idx0 = (int*)(sm + 17280);

    const int b = blockIdx.x / 1296;

    const float* kb = kxyzg + (size_t)b*KKEY*3;
    for (int i = threadIdx.x; i < KKEY; i += 256) {
        kxs[i] = kb[i*3]; kys[i] = kb[i*3+1]; kzs[i] = kb[i*3+2];
    }
    for (int i = threadIdx.x; i < 2*64*32; i += 256) {
        int sc = i >> 11, t = i & 2047, j = t >> 5, pr = t & 31;
        const float* W1 = sc ? w11 : w01;
        w1p[i] = make_float2(W1[pr*64 + j], W1[(pr+32)*64 + j]);
    }
    for (int i = threadIdx.x; i < 2*3*64; i += 256) {
        int sc = i / 192, t = i % 192, d = t / 64, o = t % 64;
        wxyz[i] = (sc ? w10 : w00)[o*131 + d];
    }
    if (threadIdx.x < 128) {
        int sc = threadIdx.x >> 6, o = threadIdx.x & 63;
        b0s[threadIdx.x] = (sc ? b10 : b00)[o];
        b1s[threadIdx.x] = (sc ? b11 : b01)[o];
    }
    __syncthreads();

    const int w = threadIdx.x >> 5, lane = threadIdx.x & 31;
    const int p  = blockIdx.x*8 + w;
    const int rp = p % NPTS;
    const float px = g_new_xyz[(size_t)p*3], py = g_new_xyz[(size_t)p*3+1],
                pz = g_new_xyz[(size_t)p*3+2];
    const float pn = fmaf(px,px, fmaf(py,py, pz*pz));

    // ---- ordered ball query ----
    const float R0 = 0.8f*0.8f, R1 = 1.6f*1.6f;
    int* l1 = idx1 + w*32;
    int* l0 = idx0 + w*16;
    int c0 = 0, c1 = 0;
    const unsigned lt = (1u << lane) - 1u;
    for (int base = 0; base < KKEY; base += 32) {
        int k = base + lane;
        float kx = kxs[k], ky = kys[k], kz = kzs[k];
        float kn  = fmaf(kx,kx, fmaf(ky,ky, kz*kz));
        float dot = fmaf(px,kx, fmaf(py,ky, pz*kz));
        float d2  = fmaf(-2.f, dot, pn + kn);
        bool v1 = d2 < R1, v0 = d2 < R0;
        unsigned m1 = __ballot_sync(0xffffffffu, v1);
        unsigned m0 = __ballot_sync(0xffffffffu, v0);
        if (c1 < 32 && m1) {
            if (v1) { int rk = c1 + __popc(m1 & lt); if (rk < 32) l1[rk] = k; }
            c1 = min(32, c1 + __popc(m1));
        }
        if (c0 < 16 && m0) {
            if (v0) { int rk = c0 + __popc(m0 & lt); if (rk < 16) l0[rk] = k; }
            c0 = min(16, c0 + __popc(m0));
        }
        if (c0 >= 16 && c1 >= 32) break;
    }
    __syncwarp();

    const int n  = rp / M_GRID, mm = rp % M_GRID;
    float* hb = h0b + w*256;

    #pragma unroll
    for (int sc = 0; sc < 2; sc++) {
        int cnt = sc ? c1 : c0;
        int* lst = sc ? l1 : l0;
        if (cnt == 0) { if (lane == 0) lst[0] = 0; cnt = 1; __syncwarp(); }

        const float* preb = g_pre + ((size_t)(sc*2 + b)*KKEY << 6);
        const float2* wp = w1p + sc*2048;
        const float* wx = wxyz + sc*192;
        const float bias0a = b0s[sc*64 + lane],  bias0b = b0s[sc*64 + lane + 32];
        const float bias1a = b1s[sc*64 + lane],  bias1b = b1s[sc*64 + lane + 32];
        const float wxa0 = wx[lane],    wxa1 = wx[64+lane],  wxa2 = wx[128+lane];
        const float wxb0 = wx[lane+32], wxb1 = wx[96+lane],  wxb2 = wx[160+lane];
        float mxa = 0.f, mxb = 0.f;

        for (int s0 = 0; s0 < cnt; s0 += 4) {
            float ha[4], hbv[4];
            #pragma unroll
            for (int s = 0; s < 4; s++) {
                int si = s0 + s;
                int k  = lst[si < cnt ? si : 0];
                float rx = kxs[k]-px, ry = kys[k]-py, rz = kzs[k]-pz;
                const float2 pr2 = *(const float2*)(preb + ((size_t)k << 6) + (lane << 1));
                float va = pr2.x + bias0a;
                va = fmaf(rx, wxa0, va);
                va = fmaf(ry, wxa1, va);
                va = fmaf(rz, wxa2, va);
                ha[s] = fmaxf(va, 0.f);
                float vb = pr2.y + bias0b;
                vb = fmaf(rx, wxb0, vb);
                vb = fmaf(ry, wxb1, vb);
                vb = fmaf(rz, wxb2, vb);
                hbv[s] = fmaxf(vb, 0.f);
            }
            *(float4*)(hb + (lane << 2))        = make_float4(ha[0],ha[1],ha[2],ha[3]);
            *(float4*)(hb + ((lane + 32) << 2)) = make_float4(hbv[0],hbv[1],hbv[2],hbv[3]);
            __syncwarp();

            float a0 = bias1a, a1 = bias1a, a2 = bias1a, a3 = bias1a;
            float e0 = bias1b, e1 = bias1b, e2 = bias1b, e3 = bias1b;
            #pragma unroll 8
            for (int j = 0; j < 64; j++) {
                float2 wv = wp[j*32 + lane];
                float4 h = *(const float4*)(hb + (j << 2));
                a0 = fmaf(wv.x, h.x, a0); a1 = fmaf(wv.x, h.y, a1);
                a2 = fmaf(wv.x, h.z, a2); a3 = fmaf(wv.x, h.w, a3);
                e0 = fmaf(wv.y, h.x, e0); e1 = fmaf(wv.y, h.y, e1);
                e2 = fmaf(wv.y, h.z, e2); e3 = fmaf(wv.y, h.w, e3);
            }
            mxa = fmaxf(mxa, fmaxf(fmaxf(a0,a1), fmaxf(a2,a3)));
            mxb = fmaxf(mxb, fmaxf(fmaxf(e0,e1), fmaxf(e2,e3)));
            __syncwarp();
        }
        size_t row = (size_t)(b*NPROP + n);
        g_pooled[row*QDIM + (size_t)(sc*64 + lane)*M_GRID + mm]      = mxa;
        g_pooled[row*QDIM + (size_t)(sc*64 + lane + 32)*M_GRID + mm] = mxb;
    }
}

// ---------------- kernel D: K-split GEMM partial = pooled @ red_w0^T ----------------
// block tile 32 rows x 64 cols; thread tile 2 rows x 4 cols (scalar FFMA)
#define XS_PITCH 34
#define WS_PITCH 68
__global__ void __launch_bounds__(256) kD(const float* __restrict__ w0) {
    __shared__ float xs[16*XS_PITCH];     // [kk][row]
    __shared__ float ws[16*WS_PITCH];     // [kk][col]
    const int tid = threadIdx.x;
    const int tx = tid & 15;              // col group (4 cols)
    const int ty = tid >> 4;              // row group (2 rows)
    const int colbase = blockIdx.x * 64;
    const int rowbase = blockIdx.y * 32;
    const int kz = blockIdx.z;

    float acc[2][4] = {};

    // gmem load indices
    const int xrow = tid >> 3, xkk = (tid & 7) << 1;       // x: float2 each
    const int wcol = tid >> 2, wk4 = (tid & 3) << 2;       // w: float4 each

    for (int kbb = 0; kbb < KCHUNK; kbb += 16) {
        int kg = kz*KCHUNK + kbb;
        {
            float2 v = *(const float2*)(g_pooled + (size_t)(rowbase + xrow)*QDIM + kg + xkk);
            xs[(xkk  )*XS_PITCH + xrow] = v.x;
            xs[(xkk+1)*XS_PITCH + xrow] = v.y;
        }
        {
            float4 v = *(const float4*)(w0 + (size_t)(colbase + wcol)*QDIM + kg + wk4);
            ws[(wk4+0)*WS_PITCH + wcol] = v.x;
            ws[(wk4+1)*WS_PITCH + wcol] = v.y;
            ws[(wk4+2)*WS_PITCH + wcol] = v.z;
            ws[(wk4+3)*WS_PITCH + wcol] = v.w;
        }
        __syncthreads();
        #pragma unroll
        for (int kk = 0; kk < 16; kk++) {
            float2 xv = *(const float2*)(xs + kk*XS_PITCH + ty*2);
            float4 wv = *(const float4*)(ws + kk*WS_PITCH + tx*4);
            acc[0][0] = fmaf(xv.x, wv.x, acc[0][0]);
            acc[0][1] = fmaf(xv.x, wv.y, acc[0][1]);
            acc[0][2] = fmaf(xv.x, wv.z, acc[0][2]);
            acc[0][3] = fmaf(xv.x, wv.w, acc[0][3]);
            acc[1][0] = fmaf(xv.y, wv.x, acc[1][0]);
            acc[1][1] = fmaf(xv.y, wv.y, acc[1][1]);
            acc[1][2] = fmaf(xv.y, wv.z, acc[1][2]);
            acc[1][3] = fmaf(xv.y, wv.w, acc[1][3]);
        }
        __syncthreads();
    }
    #pragma unroll
    for (int r = 0; r < 2; r++) {
        int row = rowbase + ty*2 + r;
        *(float4*)(g_partial + ((size_t)kz*96 + row)*256 + colbase + tx*4) =
            make_float4(acc[r][0], acc[r][1], acc[r][2], acc[r][3]);
    }
}

// ---------------- kernel E: reduce + relu + 256x256 GEMM + relu ----------------
__global__ void __launch_bounds__(256) kE(const float* __restrict__ rb0,
                                          const float* __restrict__ rw1,
                                          const float* __restrict__ rb1,
                                          float* __restrict__ out) {
    __shared__ float h2s[256];
    __shared__ float w1s[256*33];
    const int row = blockIdx.x;
    const int o = threadIdx.x;
    float s = rb0[o];
    #pragma unroll 6
    for (int ks = 0; ks < KSPLIT; ks++)
        s += g_partial[((size_t)ks*96 + row)*256 + o];
    h2s[o] = fmaxf(s, 0.f);
    __syncthreads();

    float acc = rb1[o];
    for (int jt = 0; jt < 256; jt += 32) {
        for (int i = threadIdx.x; i < 8192; i += 256) {
            int oo = i >> 5, jj = i & 31;
            w1s[oo*33 + jj] = rw1[(size_t)oo*256 + jt + jj];
        }
        __syncthreads();
        #pragma unroll
        for (int jj = 0; jj < 32; jj++)
            acc = fmaf(h2s[jt + jj], w1s[o*33 + jj], acc);
        __syncthreads();
    }
    out[(size_t)row*256 + o] = fmaxf(acc, 0.f);
}

// ---------------- launch ----------------
extern "C" void kernel_launch(void* const* d_in, const int* in_sizes, int n_in,
                              void* d_out, int out_size) {
    const float* proposals = (const float*)d_in[0];
    const float* kxyz      = (const float*)d_in[1];
    const float* kfeat     = (const float*)d_in[2];
    const float* gnoise    = (const float*)d_in[3];
    const float* w00 = (const float*)d_in[4];
    const float* b00 = (const float*)d_in[5];
    const float* w01 = (const float*)d_in[6];
    const float* b01 = (const float*)d_in[7];
    const float* w10 = (const float*)d_in[8];
    const float* b10 = (const float*)d_in[9];
    const float* w11 = (const float*)d_in[10];
    const float* b11 = (const float*)d_in[11];
    const float* rw0 = (const float*)d_in[12];
    const float* rb0 = (const float*)d_in[13];
    const float* rw1 = (const float*)d_in[14];
    const float* rb1 = (const float*)d_in[15];
    float* out = (float*)d_out;

    cudaFuncSetAttribute(kC, cudaFuncAttributeMaxDynamicSharedMemorySize,
                         KC_SMEM_WORDS * 4);

    kA<<<(NTOT + 255)/256, 256>>>(proposals, gnoise);
    kB<<<dim3(KKEY/32, 4), 256>>>(kfeat, w00, w10);
    kC<<<NTOT/8, 256, KC_SMEM_WORDS * 4>>>(kxyz, w00, b00, w01, b01,
                                           w10, b10, w11, b11);
    kD<<<dim3(256/64, 96/32, KSPLIT), 256>>>(rw0);
    kE<<<96, 256>>>(rb0, rw1, rb1, out);
}

// round 4
// speedup vs baseline: 1.6950x; 1.2715x over previous
#include <cuda_runtime.h>
#include <math.h>

#define KKEY   2048
#define CFEAT  128
#define M_GRID 216
#define NPROP  48
#define NPTS   (NPROP*M_GRID)      // 10368 per batch
#define NTOT   (2*NPTS)            // 20736
#define QDIM   (128*M_GRID)        // 27648
#define KSPLIT 54
#define KCHUNK 512

typedef unsigned long long ull;

// f32x2 kept ONLY in kB (tiny kernel, validated)
__device__ __forceinline__ ull pack2(float lo, float hi) {
    ull r; asm("mov.b64 %0, {%1, %2};" : "=l"(r) : "f"(lo), "f"(hi)); return r;
}
__device__ __forceinline__ ull ffma2(ull a, ull b, ull c) {
    ull d; asm("fma.rn.f32x2 %0, %1, %2, %3;" : "=l"(d) : "l"(a), "l"(b), "l"(c)); return d;
}
__device__ __forceinline__ float2 unpack2(ull v) {
    float2 f; asm("mov.b64 {%0, %1}, %2;" : "=f"(f.x), "=f"(f.y) : "l"(v)); return f;
}

__device__ __forceinline__ unsigned f2tf32(float v) {
    unsigned u; asm("cvt.rna.tf32.f32 %0, %1;" : "=r"(u) : "f"(v)); return u;
}
__device__ __forceinline__ void mma_tf32(float d[4], const unsigned a[4],
                                         const unsigned b[2]) {
    asm("mma.sync.aligned.m16n8k8.row.col.f32.tf32.tf32.f32 "
        "{%0,%1,%2,%3}, {%4,%5,%6,%7}, {%8,%9}, {%0,%1,%2,%3};"
        : "+f"(d[0]), "+f"(d[1]), "+f"(d[2]), "+f"(d[3])
        : "r"(a[0]), "r"(a[1]), "r"(a[2]), "r"(a[3]), "r"(b[0]), "r"(b[1]));
}

// ---------------- scratch ----------------
__device__ float g_new_xyz[NTOT*3];
__device__ float g_pre[2*2*KKEY*64];          // [scale][b][k][interleaved o]
__device__ float g_pooled[2*NPROP*QDIM];      // 96 x 27648, q = co*216+mm
__device__ float g_partial[KSPLIT*96*256];

// ---------------- kernel A ----------------
__global__ void __launch_bounds__(256) kA(const float* __restrict__ prop,
                                          const float* __restrict__ gnoise) {
    int t = blockIdx.x*256 + threadIdx.x;
    if (t >= NTOT) return;
    int b = t / NPTS, r = t % NPTS;
    int n = r / M_GRID, mm = r % M_GRID;
    const float* p = prop + (size_t)(b*NPROP + n)*7;
    const float* g = gnoise + ((size_t)(b*NPROP + n)*M_GRID + mm)*3;
    float gx = g[0]*p[3], gy = g[1]*p[4], gz = g[2]*p[5];
    float c = cosf(p[6]), s = sinf(p[6]);
    float* o = g_new_xyz + (size_t)t*3;
    o[0] = c*gx - s*gy + p[0];
    o[1] = s*gx + c*gy + p[1];
    o[2] = gz + p[2];
}

// ---------------- kernel B: pre[k][o] = W0[:,3:] . feats[:,k] ----------------
__global__ void __launch_bounds__(256) kB(const float* __restrict__ feats,
                                          const float* __restrict__ w0,
                                          const float* __restrict__ w1) {
    __shared__ float Ws[CFEAT*64];
    __shared__ float fs[CFEAT*32];
    int sb = blockIdx.y; int sc = sb >> 1, b = sb & 1;
    const float* W = sc ? w1 : w0;
    for (int i = threadIdx.x; i < CFEAT*64; i += 256) {
        int c = i >> 6, o = i & 63;
        Ws[i] = W[o*131 + 3 + c];
    }
    int kbase = blockIdx.x * 32;
    const float* fb = feats + (size_t)b*CFEAT*KKEY + kbase;
    for (int i = threadIdx.x; i < CFEAT*8; i += 256) {
        int c = i >> 3, q = i & 7;
        *(float4*)(fs + c*32 + q*4) = *(const float4*)(fb + (size_t)c*KKEY + q*4);
    }
    __syncthreads();

    int o  = threadIdx.x & 63;
    int kk = threadIdx.x >> 6;
    ull acc0 = 0, acc1 = 0, acc2 = 0, acc3 = 0;
    #pragma unroll 4
    for (int c = 0; c < CFEAT; c++) {
        float w = Ws[c*64 + o];
        ull wd = pack2(w, w);
        const ull* f = (const ull*)(fs + c*32 + kk*8);
        acc0 = ffma2(wd, f[0], acc0);
        acc1 = ffma2(wd, f[1], acc1);
        acc2 = ffma2(wd, f[2], acc2);
        acc3 = ffma2(wd, f[3], acc3);
    }
    size_t base = ((size_t)(sc*2 + b)*KKEY + kbase + kk*8) << 6;
    int oi = ((o & 31) << 1) + (o >> 5);
    float2 u;
    u = unpack2(acc0); g_pre[base + oi] = u.x; g_pre[base + 64 + oi] = u.y;
    u = unpack2(acc1); g_pre[base + 128 + oi] = u.x; g_pre[base + 192 + oi] = u.y;
    u = unpack2(acc2); g_pre[base + 256 + oi] = u.x; g_pre[base + 320 + oi] = u.y;
    u = unpack2(acc3); g_pre[base + 384 + oi] = u.x; g_pre[base + 448 + oi] = u.y;
}

// ---------------- kernel C: ball query + layer0 + tf32 MMA layer1 + maxpool --
// 512 threads = 16 warps = 16 points per block
// smem words:
//  kx 0..2048, ky ..4096, kz ..6144
//  wt[2][64*68] tf32 (j rows, o cols)      6144..14848
//  wxyz[2][3][64]                          14848..15232
//  b0s[128]                                15232..15360
//  b1s[128]                                15360..15488
//  hw[16][32*68] tf32 per warp             15488..50304
//  idx1[16][32]                            50304..50816
//  idx0[16][16]                            50816..51072
#define KC_SMEM_WORDS 51072
#define OFF_WT   6144
#define OFF_WXYZ 14848
#define OFF_B0   15232
#define OFF_B1   15360
#define OFF_HW   15488
#define OFF_IDX1 50304
#define OFF_IDX0 50816

__global__ void __launch_bounds__(512, 1) kC(
    const float* __restrict__ kxyzg,
    const float* __restrict__ w00, const float* __restrict__ b00,
    const float* __restrict__ w01, const float* __restrict__ b01,
    const float* __restrict__ w10, const float* __restrict__ b10,
    const float* __restrict__ w11, const float* __restrict__ b11)
{
    extern __shared__ float sm[];
    float*    kxs  = sm;
    float*    kys  = sm + 2048;
    float*    kzs  = sm + 4096;
    unsigned* wt   = (unsigned*)(sm + OFF_WT);
    float*    wxyz = sm + OFF_WXYZ;
    float*    b0s  = sm + OFF_B0;
    float*    b1s  = sm + OFF_B1;
    unsigned* hwg  = (unsigned*)(sm + OFF_HW);
    int*      idx1 = (int*)(sm + OFF_IDX1);
    int*      idx0 = (int*)(sm + OFF_IDX0);

    const int b = blockIdx.x / 648;           // 648 blocks per batch

    const float* kb = kxyzg + (size_t)b*KKEY*3;
    for (int i = threadIdx.x; i < KKEY; i += 512) {
        kxs[i] = kb[i*3]; kys[i] = kb[i*3+1]; kzs[i] = kb[i*3+2];
    }
    for (int i = threadIdx.x; i < 2*4096; i += 512) {
        int sc = i >> 12, t = i & 4095, j = t >> 6, o = t & 63;
        wt[sc*4352 + j*68 + o] = f2tf32((sc ? w11 : w01)[o*64 + j]);
    }
    for (int i = threadIdx.x; i < 2*3*64; i += 512) {
        int sc = i / 192, t = i % 192, d = t / 64, o = t % 64;
        wxyz[i] = (sc ? w10 : w00)[o*131 + d];
    }
    if (threadIdx.x < 256) {
        int sc = (threadIdx.x >> 6) & 1, o = threadIdx.x & 63;
        if (threadIdx.x < 128) b0s[threadIdx.x] = (sc ? b10 : b00)[o];
        else                   b1s[threadIdx.x - 128] = (sc ? b11 : b01)[o];
    }
    __syncthreads();

    const int w = threadIdx.x >> 5, lane = threadIdx.x & 31;
    const int gid = lane >> 2, tig = lane & 3;
    const int p  = blockIdx.x*16 + w;
    const int rp = p % NPTS;
    const float px = g_new_xyz[(size_t)p*3], py = g_new_xyz[(size_t)p*3+1],
                pz = g_new_xyz[(size_t)p*3+2];
    const float pn = fmaf(px,px, fmaf(py,py, pz*pz));

    // ---- ordered ball query ----
    const float R0 = 0.8f*0.8f, R1 = 1.6f*1.6f;
    int* l1 = idx1 + w*32;
    int* l0 = idx0 + w*16;
    int c0 = 0, c1 = 0;
    const unsigned lt = (1u << lane) - 1u;
    for (int base = 0; base < KKEY; base += 32) {
        int k = base + lane;
        float kx = kxs[k], ky = kys[k], kz = kzs[k];
        float kn  = fmaf(kx,kx, fmaf(ky,ky, kz*kz));
        float dot = fmaf(px,kx, fmaf(py,ky, pz*kz));
        float d2  = fmaf(-2.f, dot, pn + kn);
        bool v1 = d2 < R1, v0 = d2 < R0;
        unsigned m1 = __ballot_sync(0xffffffffu, v1);
        unsigned m0 = __ballot_sync(0xffffffffu, v0);
        if (c1 < 32 && m1) {
            if (v1) { int rk = c1 + __popc(m1 & lt); if (rk < 32) l1[rk] = k; }
            c1 = min(32, c1 + __popc(m1));
        }
        if (c0 < 16 && m0) {
            if (v0) { int rk = c0 + __popc(m0 & lt); if (rk < 16) l0[rk] = k; }
            c0 = min(16, c0 + __popc(m0));
        }
        if (c0 >= 16 && c1 >= 32) break;
    }
    __syncwarp();
    // pad lists to full nsample with first element (reference semantics)
    if (c1 == 0) { if (lane == 0) l1[0] = 0; c1 = 1; }
    if (c0 == 0) { if (lane == 0) l0[0] = 0; c0 = 1; }
    __syncwarp();
    {
        int f1 = l1[0], f0 = l0[0];
        if (lane >= c1) l1[lane] = f1;
        if (lane < 16 && lane >= c0) l0[lane] = f0;
    }
    __syncwarp();

    const int n  = rp / M_GRID, mm = rp % M_GRID;
    unsigned* hw = hwg + w*2176;       // [s][j], pitch 68

    #pragma unroll
    for (int sc = 0; sc < 2; sc++) {
        const int M = sc ? 32 : 16;
        int* lst = sc ? l1 : l0;
        const float* preb = g_pre + ((size_t)(sc*2 + b)*KKEY << 6);
        const float* wx = wxyz + sc*192;
        const float bias0a = b0s[sc*64 + lane],  bias0b = b0s[sc*64 + lane + 32];
        const float wxa0 = wx[lane],    wxa1 = wx[64+lane],  wxa2 = wx[128+lane];
        const float wxb0 = wx[lane+32], wxb1 = wx[96+lane],  wxb2 = wx[160+lane];

        // ---- layer 0 -> hw[s][j] (tf32) ----
        for (int s0 = 0; s0 < M; s0 += 4) {
            #pragma unroll
            for (int s = 0; s < 4; s++) {
                int k  = lst[s0 + s];
                float rx = kxs[k]-px, ry = kys[k]-py, rz = kzs[k]-pz;
                const float2 pr2 = *(const float2*)(preb + ((size_t)k << 6) + (lane << 1));
                float va = pr2.x + bias0a;
                va = fmaf(rx, wxa0, va);
                va = fmaf(ry, wxa1, va);
                va = fmaf(rz, wxa2, va);
                float vb = pr2.y + bias0b;
                vb = fmaf(rx, wxb0, vb);
                vb = fmaf(ry, wxb1, vb);
                vb = fmaf(rz, wxb2, vb);
                hw[(s0+s)*68 + lane]      = f2tf32(fmaxf(va, 0.f));
                hw[(s0+s)*68 + 32 + lane] = f2tf32(fmaxf(vb, 0.f));
            }
        }
        __syncwarp();

        // ---- layer 1 via tf32 mma + row-max fold ----
        const unsigned* wts = wt + sc*4352;
        float cm0[8], cm1[8];
        #pragma unroll
        for (int nt = 0; nt < 8; nt++) { cm0[nt] = -3.4e38f; cm1[nt] = -3.4e38f; }

        const int MT = sc ? 2 : 1;
        for (int mt = 0; mt < MT; mt++) {
            float acc[8][4];
            #pragma unroll
            for (int nt = 0; nt < 8; nt++)
                acc[nt][0] = acc[nt][1] = acc[nt][2] = acc[nt][3] = 0.f;
            #pragma unroll
            for (int kt = 0; kt < 8; kt++) {
                unsigned a[4];
                const unsigned* hrow = hw + (mt*16 + gid)*68 + kt*8 + tig;
                a[0] = hrow[0];
                a[1] = hrow[8*68];
                a[2] = hrow[4];
                a[3] = hrow[8*68 + 4];
                #pragma unroll
                for (int nt = 0; nt < 8; nt++) {
                    unsigned bb[2];
                    const unsigned* wrow = wts + (kt*8 + tig)*68 + nt*8 + gid;
                    bb[0] = wrow[0];
                    bb[1] = wrow[4*68];
                    mma_tf32(acc[nt], a, bb);
                }
            }
            #pragma unroll
            for (int nt = 0; nt < 8; nt++) {
                cm0[nt] = fmaxf(cm0[nt], fmaxf(acc[nt][0], acc[nt][2]));
                cm1[nt] = fmaxf(cm1[nt], fmaxf(acc[nt][1], acc[nt][3]));
            }
        }
        // reduce across the 8 row-groups (lane bits 2..4)
        #pragma unroll
        for (int off = 4; off <= 16; off <<= 1) {
            #pragma unroll
            for (int nt = 0; nt < 8; nt++) {
                cm0[nt] = fmaxf(cm0[nt], __shfl_xor_sync(0xffffffffu, cm0[nt], off));
                cm1[nt] = fmaxf(cm1[nt], __shfl_xor_sync(0xffffffffu, cm1[nt], off));
            }
        }
        // epilogue: bias + relu + scatter (lanes 0-3 write, replicas elsewhere)
        size_t rowb = (size_t)(b*NPROP + n)*QDIM + (size_t)sc*64*M_GRID + mm;
        if (gid == 0) {
            #pragma unroll
            for (int nt = 0; nt < 8; nt++) {
                int o0 = nt*8 + tig*2;
                float v0 = fmaxf(cm0[nt] + b1s[sc*64 + o0],     0.f);
                float v1 = fmaxf(cm1[nt] + b1s[sc*64 + o0 + 1], 0.f);
                g_pooled[rowb + (size_t)o0*M_GRID]       = v0;
                g_pooled[rowb + (size_t)(o0+1)*M_GRID]   = v1;
            }
        }
        __syncwarp();
    }
}

// ---------------- kernel D: K-split GEMM with reg prefetch ----------------
#define KD_KT 32
#define XS_PITCH 34
#define WS_PITCH 68
__global__ void __launch_bounds__(256) kD(const float* __restrict__ w0) {
    __shared__ float xs[2][KD_KT*XS_PITCH];
    __shared__ float ws[2][KD_KT*WS_PITCH];
    const int tid = threadIdx.x;
    const int tx = tid & 15, ty = tid >> 4;
    const int colbase = blockIdx.x * 64;
    const int rowbase = blockIdx.y * 32;
    const int kg0 = blockIdx.z * KCHUNK;

    const int xrow = tid >> 3, xkq = (tid & 7) << 2;
    const int wcol = tid >> 3, wkq = (tid & 7) << 2;

    const float* xg = g_pooled + (size_t)(rowbase + xrow)*QDIM + kg0 + xkq;
    const float* wg0 = w0 + (size_t)(colbase + wcol)*QDIM + kg0 + wkq;
    const float* wg1 = w0 + (size_t)(colbase + wcol + 32)*QDIM + kg0 + wkq;

    float4 xv4  = *(const float4*)xg;
    float4 wv4a = *(const float4*)wg0;
    float4 wv4b = *(const float4*)wg1;

    float acc[2][4] = {};
    const int NT = KCHUNK / KD_KT;           // 16
    for (int t = 0; t < NT; t++) {
        float* xsc = xs[t & 1];
        float* wsc = ws[t & 1];
        xsc[(xkq+0)*XS_PITCH + xrow] = xv4.x;
        xsc[(xkq+1)*XS_PITCH + xrow] = xv4.y;
        xsc[(xkq+2)*XS_PITCH + xrow] = xv4.z;
        xsc[(xkq+3)*XS_PITCH + xrow] = xv4.w;
        wsc[(wkq+0)*WS_PITCH + wcol] = wv4a.x;
        wsc[(wkq+1)*WS_PITCH + wcol] = wv4a.y;
        wsc[(wkq+2)*WS_PITCH + wcol] = wv4a.z;
        wsc[(wkq+3)*WS_PITCH + wcol] = wv4a.w;
        wsc[(wkq+0)*WS_PITCH + wcol + 32] = wv4b.x;
        wsc[(wkq+1)*WS_PITCH + wcol + 32] = wv4b.y;
        wsc[(wkq+2)*WS_PITCH + wcol + 32] = wv4b.z;
        wsc[(wkq+3)*WS_PITCH + wcol + 32] = wv4b.w;
        __syncthreads();
        if (t + 1 < NT) {
            int d = (t + 1) * KD_KT;
            xv4  = *(const float4*)(xg + d);
            wv4a = *(const float4*)(wg0 + d);
            wv4b = *(const float4*)(wg1 + d);
        }
        #pragma unroll
        for (int kk = 0; kk < KD_KT; kk++) {
            float2 xv = *(const float2*)(xsc + kk*XS_PITCH + ty*2);
            float4 wv = *(const float4*)(wsc + kk*WS_PITCH + tx*4);
            acc[0][0] = fmaf(xv.x, wv.x, acc[0][0]);
            acc[0][1] = fmaf(xv.x, wv.y, acc[0][1]);
            acc[0][2] = fmaf(xv.x, wv.z, acc[0][2]);
            acc[0][3] = fmaf(xv.x, wv.w, acc[0][3]);
            acc[1][0] = fmaf(xv.y, wv.x, acc[1][0]);
            acc[1][1] = fmaf(xv.y, wv.y, acc[1][1]);
            acc[1][2] = fmaf(xv.y, wv.z, acc[1][2]);
            acc[1][3] = fmaf(xv.y, wv.w, acc[1][3]);
        }
        __syncthreads();
    }
    #pragma unroll
    for (int r = 0; r < 2; r++) {
        int row = rowbase + ty*2 + r;
        *(float4*)(g_partial + ((size_t)blockIdx.z*96 + row)*256 + colbase + tx*4) =
            make_float4(acc[r][0], acc[r][1], acc[r][2], acc[r][3]);
    }
}

// ---------------- kernel E: reduce + relu + 256x256 GEMM + relu ----------------
__global__ void __launch_bounds__(256) kE(const float* __restrict__ rb0,
                                          const float* __restrict__ rw1,
                                          const float* __restrict__ rb1,
                                          float* __restrict__ out) {
    __shared__ float h2s[256];
    __shared__ float w1s[256*33];
    const int row = blockIdx.x;
    const int o = threadIdx.x;
    float s = rb0[o];
    #pragma unroll 6
    for (int ks = 0; ks < KSPLIT; ks++)
        s += g_partial[((size_t)ks*96 + row)*256 + o];
    h2s[o] = fmaxf(s, 0.f);
    __syncthreads();

    float acc = rb1[o];
    for (int jt = 0; jt < 256; jt += 32) {
        for (int i = threadIdx.x; i < 8192; i += 256) {
            int oo = i >> 5, jj = i & 31;
            w1s[oo*33 + jj] = rw1[(size_t)oo*256 + jt + jj];
        }
        __syncthreads();
        #pragma unroll
        for (int jj = 0; jj < 32; jj++)
            acc = fmaf(h2s[jt + jj], w1s[o*33 + jj], acc);
        __syncthreads();
    }
    out[(size_t)row*256 + o] = fmaxf(acc, 0.f);
}

// ---------------- launch ----------------
extern "C" void kernel_launch(void* const* d_in, const int* in_sizes, int n_in,
                              void* d_out, int out_size) {
    const float* proposals = (const float*)d_in[0];
    const float* kxyz      = (const float*)d_in[1];
    const float* kfeat     = (const float*)d_in[2];
    const float* gnoise    = (const float*)d_in[3];
    const float* w00 = (const float*)d_in[4];
    const float* b00 = (const float*)d_in[5];
    const float* w01 = (const float*)d_in[6];
    const float* b01 = (const float*)d_in[7];
    const float* w10 = (const float*)d_in[8];
    const float* b10 = (const float*)d_in[9];
    const float* w11 = (const float*)d_in[10];
    const float* b11 = (const float*)d_in[11];
    const float* rw0 = (const float*)d_in[12];
    const float* rb0 = (const float*)d_in[13];
    const float* rw1 = (const float*)d_in[14];
    const float* rb1 = (const float*)d_in[15];
    float* out = (float*)d_out;

    cudaFuncSetAttribute(kC, cudaFuncAttributeMaxDynamicSharedMemorySize,
                         KC_SMEM_WORDS * 4);

    kA<<<(NTOT + 255)/256, 256>>>(proposals, gnoise);
    kB<<<dim3(KKEY/32, 4), 256>>>(kfeat, w00, w10);
    kC<<<NTOT/16, 512, KC_SMEM_WORDS * 4>>>(kxyz, w00, b00, w01, b01,
                                            w10, b10, w11, b11);
    kD<<<dim3(256/64, 96/32, KSPLIT), 256>>>(rw0);
    kE<<<96, 256>>>(rb0, rw1, rb1, out);
}

// round 5
// speedup vs baseline: 2.3177x; 1.3674x over previous
#include <cuda_runtime.h>
#include <math.h>

#define KKEY   2048
#define CFEAT  128
#define M_GRID 216
#define NPROP  48
#define NPTS   (NPROP*M_GRID)      // 10368 per batch
#define NTOT   (2*NPTS)            // 20736
#define QDIM   (128*M_GRID)        // 27648
#define KSPLIT 108
#define KCHUNK 256

typedef unsigned long long ull;

__device__ __forceinline__ ull pack2(float lo, float hi) {
    ull r; asm("mov.b64 %0, {%1, %2};" : "=l"(r) : "f"(lo), "f"(hi)); return r;
}
__device__ __forceinline__ ull ffma2(ull a, ull b, ull c) {
    ull d; asm("fma.rn.f32x2 %0, %1, %2, %3;" : "=l"(d) : "l"(a), "l"(b), "l"(c)); return d;
}
__device__ __forceinline__ float2 unpack2(ull v) {
    float2 f; asm("mov.b64 {%0, %1}, %2;" : "=f"(f.x), "=f"(f.y) : "l"(v)); return f;
}
__device__ __forceinline__ unsigned f2tf32(float v) {
    unsigned u; asm("cvt.rna.tf32.f32 %0, %1;" : "=r"(u) : "f"(v)); return u;
}
__device__ __forceinline__ void mma_tf32(float d[4], const unsigned a[4],
                                         const unsigned b[2]) {
    asm("mma.sync.aligned.m16n8k8.row.col.f32.tf32.tf32.f32 "
        "{%0,%1,%2,%3}, {%4,%5,%6,%7}, {%8,%9}, {%0,%1,%2,%3};"
        : "+f"(d[0]), "+f"(d[1]), "+f"(d[2]), "+f"(d[3])
        : "r"(a[0]), "r"(a[1]), "r"(a[2]), "r"(a[3]), "r"(b[0]), "r"(b[1]));
}

// ---------------- scratch ----------------
__device__ float  g_new_xyz[NTOT*3];
__device__ float  g_pre[2*2*KKEY*64];        // [scale][b][k][interleaved o]
__device__ float4 g_rel1[NTOT*32];           // {rx,ry,rz, bitcast k}
__device__ float4 g_rel0[NTOT*16];
__device__ float  g_pooled[2*NPROP*QDIM];    // 96 x 27648, q = co*216+mm
__device__ float  g_partial[KSPLIT*96*256];

// ---------------- kernel A ----------------
__global__ void __launch_bounds__(256) kA(const float* __restrict__ prop,
                                          const float* __restrict__ gnoise) {
    int t = blockIdx.x*256 + threadIdx.x;
    if (t >= NTOT) return;
    int b = t / NPTS, r = t % NPTS;
    int n = r / M_GRID, mm = r % M_GRID;
    const float* p = prop + (size_t)(b*NPROP + n)*7;
    const float* g = gnoise + ((size_t)(b*NPROP + n)*M_GRID + mm)*3;
    float gx = g[0]*p[3], gy = g[1]*p[4], gz = g[2]*p[5];
    float c = cosf(p[6]), s = sinf(p[6]);
    float* o = g_new_xyz + (size_t)t*3;
    o[0] = c*gx - s*gy + p[0];
    o[1] = s*gx + c*gy + p[1];
    o[2] = gz + p[2];
}

// ---------------- kernel B: pre[k][o] = W0[:,3:] . feats[:,k] ----------------
__global__ void __launch_bounds__(256) kB(const float* __restrict__ feats,
                                          const float* __restrict__ w0,
                                          const float* __restrict__ w1) {
    __shared__ float Ws[CFEAT*64];
    __shared__ float fs[CFEAT*32];
    int sb = blockIdx.y; int sc = sb >> 1, b = sb & 1;
    const float* W = sc ? w1 : w0;
    for (int i = threadIdx.x; i < CFEAT*64; i += 256) {
        int c = i >> 6, o = i & 63;
        Ws[i] = W[o*131 + 3 + c];
    }
    int kbase = blockIdx.x * 32;
    const float* fb = feats + (size_t)b*CFEAT*KKEY + kbase;
    for (int i = threadIdx.x; i < CFEAT*8; i += 256) {
        int c = i >> 3, q = i & 7;
        *(float4*)(fs + c*32 + q*4) = *(const float4*)(fb + (size_t)c*KKEY + q*4);
    }
    __syncthreads();

    int o  = threadIdx.x & 63;
    int kk = threadIdx.x >> 6;
    ull acc0 = 0, acc1 = 0, acc2 = 0, acc3 = 0;
    #pragma unroll 4
    for (int c = 0; c < CFEAT; c++) {
        float w = Ws[c*64 + o];
        ull wd = pack2(w, w);
        const ull* f = (const ull*)(fs + c*32 + kk*8);
        acc0 = ffma2(wd, f[0], acc0);
        acc1 = ffma2(wd, f[1], acc1);
        acc2 = ffma2(wd, f[2], acc2);
        acc3 = ffma2(wd, f[3], acc3);
    }
    size_t base = ((size_t)(sc*2 + b)*KKEY + kbase + kk*8) << 6;
    int oi = ((o & 31) << 1) + (o >> 5);
    float2 u;
    u = unpack2(acc0); g_pre[base + oi] = u.x; g_pre[base + 64 + oi] = u.y;
    u = unpack2(acc1); g_pre[base + 128 + oi] = u.x; g_pre[base + 192 + oi] = u.y;
    u = unpack2(acc2); g_pre[base + 256 + oi] = u.x; g_pre[base + 320 + oi] = u.y;
    u = unpack2(acc3); g_pre[base + 384 + oi] = u.x; g_pre[base + 448 + oi] = u.y;
}

// ---------------- kernel Q: ball query -> padded idx + rel coords ----------
__global__ void __launch_bounds__(256) kQ(const float* __restrict__ kxyzg) {
    __shared__ float kxs[KKEY], kys[KKEY], kzs[KKEY];
    __shared__ int idx1s[8][32], idx0s[8][16];

    const int b = blockIdx.x / 1296;
    const float* kb = kxyzg + (size_t)b*KKEY*3;
    for (int i = threadIdx.x; i < KKEY; i += 256) {
        kxs[i] = kb[i*3]; kys[i] = kb[i*3+1]; kzs[i] = kb[i*3+2];
    }
    __syncthreads();

    const int w = threadIdx.x >> 5, lane = threadIdx.x & 31;
    const int p = blockIdx.x*8 + w;
    const float px = g_new_xyz[(size_t)p*3], py = g_new_xyz[(size_t)p*3+1],
                pz = g_new_xyz[(size_t)p*3+2];
    const float pn = fmaf(px,px, fmaf(py,py, pz*pz));

    const float R0 = 0.8f*0.8f, R1 = 1.6f*1.6f;
    int* l1 = idx1s[w];
    int* l0 = idx0s[w];
    int c0 = 0, c1 = 0;
    const unsigned lt = (1u << lane) - 1u;
    for (int base = 0; base < KKEY; base += 32) {
        int k = base + lane;
        float kx = kxs[k], ky = kys[k], kz = kzs[k];
        float kn  = fmaf(kx,kx, fmaf(ky,ky, kz*kz));
        float dot = fmaf(px,kx, fmaf(py,ky, pz*kz));
        float d2  = fmaf(-2.f, dot, pn + kn);
        bool v1 = d2 < R1, v0 = d2 < R0;
        unsigned m1 = __ballot_sync(0xffffffffu, v1);
        unsigned m0 = __ballot_sync(0xffffffffu, v0);
        if (c1 < 32 && m1) {
            if (v1) { int rk = c1 + __popc(m1 & lt); if (rk < 32) l1[rk] = k; }
            c1 = min(32, c1 + __popc(m1));
        }
        if (c0 < 16 && m0) {
            if (v0) { int rk = c0 + __popc(m0 & lt); if (rk < 16) l0[rk] = k; }
            c0 = min(16, c0 + __popc(m0));
        }
        if (c0 >= 16 && c1 >= 32) break;
    }
    __syncwarp();
    if (c1 == 0) { if (lane == 0) l1[0] = 0; c1 = 1; }
    if (c0 == 0) { if (lane == 0) l0[0] = 0; c0 = 1; }
    __syncwarp();
    {
        int f1 = l1[0], f0 = l0[0];
        if (lane >= c1) l1[lane] = f1;
        if (lane < 16 && lane >= c0) l0[lane] = f0;
    }
    __syncwarp();

    {
        int k = l1[lane];
        g_rel1[(size_t)p*32 + lane] =
            make_float4(kxs[k]-px, kys[k]-py, kzs[k]-pz, __int_as_float(k));
        if (lane < 16) {
            int k0 = l0[lane];
            g_rel0[(size_t)p*16 + lane] =
                make_float4(kxs[k0]-px, kys[k0]-py, kzs[k0]-pz, __int_as_float(k0));
        }
    }
}

// ---------------- kernel C2: layer0 + tf32 MMA layer1 + maxpool ------------
// 384 threads = 12 warps = 12 points/block; dyn smem words:
//  wt[2][64*72] tf32                 0     .. 9216
//  wxyz[2][3][64]                    9216  .. 9600
//  b0s[128]                          9600  .. 9728
//  b1s[128]                          9728  .. 9856
//  hw[12][16*68]                     9856  .. 22912
#define KC2_SMEM_WORDS 22912
#define OFF2_WXYZ 9216
#define OFF2_B0   9600
#define OFF2_B1   9728
#define OFF2_HW   9856

__global__ void __launch_bounds__(384, 2) kC2(
    const float* __restrict__ w00, const float* __restrict__ b00,
    const float* __restrict__ w01, const float* __restrict__ b01,
    const float* __restrict__ w10, const float* __restrict__ b10,
    const float* __restrict__ w11, const float* __restrict__ b11)
{
    extern __shared__ float sm[];
    unsigned* wt   = (unsigned*)sm;
    float*    wxyz = sm + OFF2_WXYZ;
    float*    b0s  = sm + OFF2_B0;
    float*    b1s  = sm + OFF2_B1;
    unsigned* hwg  = (unsigned*)(sm + OFF2_HW);

    for (int i = threadIdx.x; i < 2*4096; i += 384) {
        int sc = i >> 12, t = i & 4095, j = t >> 6, o = t & 63;
        wt[sc*4608 + j*72 + o] = f2tf32((sc ? w11 : w01)[o*64 + j]);
    }
    for (int i = threadIdx.x; i < 2*3*64; i += 384) {
        int sc = i / 192, t = i % 192, d = t / 64, o = t % 64;
        wxyz[i] = (sc ? w10 : w00)[o*131 + d];
    }
    if (threadIdx.x < 256) {
        int sc = (threadIdx.x >> 6) & 1, o = threadIdx.x & 63;
        if (threadIdx.x < 128) b0s[threadIdx.x] = (sc ? b10 : b00)[o];
        else                   b1s[threadIdx.x - 128] = (sc ? b11 : b01)[o];
    }
    __syncthreads();

    const int w = threadIdx.x >> 5, lane = threadIdx.x & 31;
    const int gid = lane >> 2, tig = lane & 3;
    const int p  = blockIdx.x*12 + w;
    const int b  = p / NPTS;
    const int rp = p % NPTS;
    const int n  = rp / M_GRID, mm = rp % M_GRID;

    const float4 r1 = g_rel1[(size_t)p*32 + lane];
    float4 r0 = make_float4(0.f,0.f,0.f,0.f);
    if (lane < 16) r0 = g_rel0[(size_t)p*16 + lane];

    unsigned* hw = hwg + w*1088;       // [s 0..15][j], pitch 68

    #pragma unroll
    for (int sc = 0; sc < 2; sc++) {
        const int NPASS = sc ? 2 : 1;
        const float* preb = g_pre + ((size_t)(sc*2 + b)*KKEY << 6);
        const unsigned* wts = wt + sc*4608;
        const float* wx = wxyz + sc*192;
        const float bias0a = b0s[sc*64 + lane],  bias0b = b0s[sc*64 + lane + 32];
        const float wxa0 = wx[lane],    wxa1 = wx[64+lane],  wxa2 = wx[128+lane];
        const float wxb0 = wx[lane+32], wxb1 = wx[96+lane],  wxb2 = wx[160+lane];
        const float4 rr = sc ? r1 : r0;

        float cm0[8], cm1[8];
        #pragma unroll
        for (int nt = 0; nt < 8; nt++) { cm0[nt] = -3.4e38f; cm1[nt] = -3.4e38f; }

        for (int pass = 0; pass < NPASS; pass++) {
            // ---- layer 0: 16 samples -> hw ----
            #pragma unroll
            for (int s0 = 0; s0 < 16; s0 += 4) {
                #pragma unroll
                for (int s = 0; s < 4; s++) {
                    int si = pass*16 + s0 + s;
                    float rx = __shfl_sync(0xffffffffu, rr.x, si);
                    float ry = __shfl_sync(0xffffffffu, rr.y, si);
                    float rz = __shfl_sync(0xffffffffu, rr.z, si);
                    int k = __float_as_int(__shfl_sync(0xffffffffu, rr.w, si));
                    const float2 pr2 = *(const float2*)(preb + ((size_t)k << 6) + (lane << 1));
                    float va = pr2.x + bias0a;
                    va = fmaf(rx, wxa0, va);
                    va = fmaf(ry, wxa1, va);
                    va = fmaf(rz, wxa2, va);
                    float vb = pr2.y + bias0b;
                    vb = fmaf(rx, wxb0, vb);
                    vb = fmaf(ry, wxb1, vb);
                    vb = fmaf(rz, wxb2, vb);
                    hw[(s0+s)*68 + lane]      = f2tf32(fmaxf(va, 0.f));
                    hw[(s0+s)*68 + 32 + lane] = f2tf32(fmaxf(vb, 0.f));
                }
            }
            __syncwarp();

            // ---- layer 1 MMA over this 16-sample tile ----
            float acc[8][4];
            #pragma unroll
            for (int nt = 0; nt < 8; nt++)
                acc[nt][0] = acc[nt][1] = acc[nt][2] = acc[nt][3] = 0.f;
            #pragma unroll
            for (int kt = 0; kt < 8; kt++) {
                unsigned a[4];
                const unsigned* hrow = hw + gid*68 + kt*8 + tig;
                a[0] = hrow[0];
                a[1] = hrow[8*68];
                a[2] = hrow[4];
                a[3] = hrow[8*68 + 4];
                #pragma unroll
                for (int nt = 0; nt < 8; nt++) {
                    unsigned bb[2];
                    const unsigned* wrow = wts + (kt*8 + tig)*72 + nt*8 + gid;
                    bb[0] = wrow[0];
                    bb[1] = wrow[4*72];
                    mma_tf32(acc[nt], a, bb);
                }
            }
            #pragma unroll
            for (int nt = 0; nt < 8; nt++) {
                cm0[nt] = fmaxf(cm0[nt], fmaxf(acc[nt][0], acc[nt][2]));
                cm1[nt] = fmaxf(cm1[nt], fmaxf(acc[nt][1], acc[nt][3]));
            }
            __syncwarp();
        }

        // reduce across row-groups (lane bits 2..4)
        #pragma unroll
        for (int off = 4; off <= 16; off <<= 1) {
            #pragma unroll
            for (int nt = 0; nt < 8; nt++) {
                cm0[nt] = fmaxf(cm0[nt], __shfl_xor_sync(0xffffffffu, cm0[nt], off));
                cm1[nt] = fmaxf(cm1[nt], __shfl_xor_sync(0xffffffffu, cm1[nt], off));
            }
        }
        size_t rowb = (size_t)(b*NPROP + n)*QDIM + (size_t)sc*64*M_GRID + mm;
        if (gid == 0) {
            #pragma unroll
            for (int nt = 0; nt < 8; nt++) {
                int o0 = nt*8 + tig*2;
                float v0 = fmaxf(cm0[nt] + b1s[sc*64 + o0],     0.f);
                float v1 = fmaxf(cm1[nt] + b1s[sc*64 + o0 + 1], 0.f);
                g_pooled[rowb + (size_t)o0*M_GRID]     = v0;
                g_pooled[rowb + (size_t)(o0+1)*M_GRID] = v1;
            }
        }
    }
}

// ---------------- kernel D: K-split GEMM, 4x8 thread tile -------------------
#define KD_KT 16
#define XSP 36
#define WSP 260
__global__ void __launch_bounds__(256) kD(const float* __restrict__ w0) {
    __shared__ float xs[2][KD_KT*XSP];
    __shared__ float ws[2][KD_KT*WSP];
    const int tid = threadIdx.x;
    const int tx = tid & 31, ty = tid >> 5;
    const int rowbase = blockIdx.y * 32;
    const int kg0 = blockIdx.z * KCHUNK;

    const int xrow = tid >> 3, xk = (tid & 7) << 1;
    const int wcol = tid >> 2, wk = (tid & 3) << 2;

    const float* xg = g_pooled + (size_t)(rowbase + xrow)*QDIM + kg0 + xk;
    const float* wg0 = w0 + (size_t)(wcol      )*QDIM + kg0 + wk;
    const float* wg1 = w0 + (size_t)(wcol +  64)*QDIM + kg0 + wk;
    const float* wg2 = w0 + (size_t)(wcol + 128)*QDIM + kg0 + wk;
    const float* wg3 = w0 + (size_t)(wcol + 192)*QDIM + kg0 + wk;

    float2 xv = *(const float2*)xg;
    float4 wv0 = *(const float4*)wg0;
    float4 wv1 = *(const float4*)wg1;
    float4 wv2 = *(const float4*)wg2;
    float4 wv3 = *(const float4*)wg3;

    float acc[4][8] = {};
    const int NT = KCHUNK / KD_KT;      // 16
    for (int t = 0; t < NT; t++) {
        float* xsc = xs[t & 1];
        float* wsc = ws[t & 1];
        xsc[(xk  )*XSP + xrow] = xv.x;
        xsc[(xk+1)*XSP + xrow] = xv.y;
        #pragma unroll
        for (int j = 0; j < 4; j++) {
            wsc[(wk+j)*WSP + wcol      ] = ((const float*)&wv0)[j];
            wsc[(wk+j)*WSP + wcol +  64] = ((const float*)&wv1)[j];
            wsc[(wk+j)*WSP + wcol + 128] = ((const float*)&wv2)[j];
            wsc[(wk+j)*WSP + wcol + 192] = ((const float*)&wv3)[j];
        }
        __syncthreads();
        if (t + 1 < NT) {
            int d = (t + 1) * KD_KT;
            xv  = *(const float2*)(xg + d);
            wv0 = *(const float4*)(wg0 + d);
            wv1 = *(const float4*)(wg1 + d);
            wv2 = *(const float4*)(wg2 + d);
            wv3 = *(const float4*)(wg3 + d);
        }
        #pragma unroll
        for (int kk = 0; kk < KD_KT; kk++) {
            float4 xq = *(const float4*)(xsc + kk*XSP + ty*4);
            float4 wa = *(const float4*)(wsc + kk*WSP + tx*4);
            float4 wb = *(const float4*)(wsc + kk*WSP + 128 + tx*4);
            const float xr[4] = {xq.x, xq.y, xq.z, xq.w};
            const float wc[8] = {wa.x, wa.y, wa.z, wa.w, wb.x, wb.y, wb.z, wb.w};
            #pragma unroll
            for (int i = 0; i < 4; i++)
                #pragma unroll
                for (int j = 0; j < 8; j++)
                    acc[i][j] = fmaf(xr[i], wc[j], acc[i][j]);
        }
        __syncthreads();
    }
    #pragma unroll
    for (int i = 0; i < 4; i++) {
        int row = rowbase + ty*4 + i;
        float* pp = g_partial + ((size_t)blockIdx.z*96 + row)*256;
        *(float4*)(pp + tx*4)       = make_float4(acc[i][0], acc[i][1], acc[i][2], acc[i][3]);
        *(float4*)(pp + 128 + tx*4) = make_float4(acc[i][4], acc[i][5], acc[i][6], acc[i][7]);
    }
}

// ---------------- kernel E: reduce + relu + 256x256 GEMM + relu ------------
__global__ void __launch_bounds__(256) kE(const float* __restrict__ rb0,
                                          const float* __restrict__ rw1,
                                          const float* __restrict__ rb1,
                                          float* __restrict__ out) {
    __shared__ float h2s[256];
    __shared__ float w1s[256*33];
    const int row = blockIdx.x;
    const int o = threadIdx.x;
    float s = rb0[o];
    #pragma unroll 4
    for (int ks = 0; ks < KSPLIT; ks++)
        s += g_partial[((size_t)ks*96 + row)*256 + o];
    h2s[o] = fmaxf(s, 0.f);
    __syncthreads();

    float acc = rb1[o];
    for (int jt = 0; jt < 256; jt += 32) {
        for (int i = threadIdx.x; i < 8192; i += 256) {
            int oo = i >> 5, jj = i & 31;
            w1s[oo*33 + jj] = rw1[(size_t)oo*256 + jt + jj];
        }
        __syncthreads();
        #pragma unroll
        for (int jj = 0; jj < 32; jj++)
            acc = fmaf(h2s[jt + jj], w1s[o*33 + jj], acc);
        __syncthreads();
    }
    out[(size_t)row*256 + o] = fmaxf(acc, 0.f);
}

// ---------------- launch ----------------
extern "C" void kernel_launch(void* const* d_in, const int* in_sizes, int n_in,
                              void* d_out, int out_size) {
    const float* proposals = (const float*)d_in[0];
    const float* kxyz      = (const float*)d_in[1];
    const float* kfeat     = (const float*)d_in[2];
    const float* gnoise    = (const float*)d_in[3];
    const float* w00 = (const float*)d_in[4];
    const float* b00 = (const float*)d_in[5];
    const float* w01 = (const float*)d_in[6];
    const float* b01 = (const float*)d_in[7];
    const float* w10 = (const float*)d_in[8];
    const float* b10 = (const float*)d_in[9];
    const float* w11 = (const float*)d_in[10];
    const float* b11 = (const float*)d_in[11];
    const float* rw0 = (const float*)d_in[12];
    const float* rb0 = (const float*)d_in[13];
    const float* rw1 = (const float*)d_in[14];
    const float* rb1 = (const float*)d_in[15];
    float* out = (float*)d_out;

    cudaFuncSetAttribute(kC2, cudaFuncAttributeMaxDynamicSharedMemorySize,
                         KC2_SMEM_WORDS * 4);

    kA<<<(NTOT + 255)/256, 256>>>(proposals, gnoise);
    kB<<<dim3(KKEY/32, 4), 256>>>(kfeat, w00, w10);
    kQ<<<NTOT/8, 256>>>(kxyz);
    kC2<<<NTOT/12, 384, KC2_SMEM_WORDS * 4>>>(w00, b00, w01, b01,
                                              w10, b10, w11, b11);
    kD<<<dim3(1, 96/32, KSPLIT), 256>>>(rw0);
    kE<<<96, 256>>>(rb0, rw1, rb1, out);
}

// round 6
// speedup vs baseline: 2.7499x; 1.1865x over previous
#include <cuda_runtime.h>
#include <math.h>

#define KKEY   2048
#define CFEAT  128
#define M_GRID 216
#define NPROP  48
#define NPTS   (NPROP*M_GRID)      // 10368 per batch
#define NTOT   (2*NPTS)            // 20736
#define QDIM   (128*M_GRID)        // 27648
#define KSPLIT 108
#define KCHUNK 256

typedef unsigned long long ull;

__device__ __forceinline__ ull pack2(float lo, float hi) {
    ull r; asm("mov.b64 %0, {%1, %2};" : "=l"(r) : "f"(lo), "f"(hi)); return r;
}
__device__ __forceinline__ ull ffma2(ull a, ull b, ull c) {
    ull d; asm("fma.rn.f32x2 %0, %1, %2, %3;" : "=l"(d) : "l"(a), "l"(b), "l"(c)); return d;
}
__device__ __forceinline__ float2 unpack2(ull v) {
    float2 f; asm("mov.b64 {%0, %1}, %2;" : "=f"(f.x), "=f"(f.y) : "l"(v)); return f;
}
__device__ __forceinline__ unsigned f2tf32(float v) {
    unsigned u; asm("cvt.rna.tf32.f32 %0, %1;" : "=r"(u) : "f"(v)); return u;
}
__device__ __forceinline__ void mma_tf32(float d[4], const unsigned a[4],
                                         const unsigned b0, const unsigned b1) {
    asm("mma.sync.aligned.m16n8k8.row.col.f32.tf32.tf32.f32 "
        "{%0,%1,%2,%3}, {%4,%5,%6,%7}, {%8,%9}, {%0,%1,%2,%3};"
        : "+f"(d[0]), "+f"(d[1]), "+f"(d[2]), "+f"(d[3])
        : "r"(a[0]), "r"(a[1]), "r"(a[2]), "r"(a[3]), "r"(b0), "r"(b1));
}

// ---------------- scratch ----------------
__device__ float  g_new_xyz[NTOT*3];
__device__ float  g_pre[2*2*KKEY*64];        // [scale][b][k][interleaved o]
__device__ float4 g_rel1[NTOT*32];           // {rx,ry,rz, bitcast k}
__device__ float4 g_rel0[NTOT*16];
__device__ float  g_pooled[2*NPROP*QDIM];    // 96 x 27648, q = co*216+mm
__device__ float  g_partial[KSPLIT*96*256];

// ---------------- kernel A ----------------
__global__ void __launch_bounds__(256) kA(const float* __restrict__ prop,
                                          const float* __restrict__ gnoise) {
    int t = blockIdx.x*256 + threadIdx.x;
    if (t >= NTOT) return;
    int b = t / NPTS, r = t % NPTS;
    int n = r / M_GRID, mm = r % M_GRID;
    const float* p = prop + (size_t)(b*NPROP + n)*7;
    const float* g = gnoise + ((size_t)(b*NPROP + n)*M_GRID + mm)*3;
    float gx = g[0]*p[3], gy = g[1]*p[4], gz = g[2]*p[5];
    float c = cosf(p[6]), s = sinf(p[6]);
    float* o = g_new_xyz + (size_t)t*3;
    o[0] = c*gx - s*gy + p[0];
    o[1] = s*gx + c*gy + p[1];
    o[2] = gz + p[2];
}

// ---------------- kernel B: pre[k][o] = W0[:,3:] . feats[:,k] ----------------
__global__ void __launch_bounds__(256) kB(const float* __restrict__ feats,
                                          const float* __restrict__ w0,
                                          const float* __restrict__ w1) {
    __shared__ float Ws[CFEAT*64];
    __shared__ float fs[CFEAT*32];
    int sb = blockIdx.y; int sc = sb >> 1, b = sb & 1;
    const float* W = sc ? w1 : w0;
    for (int i = threadIdx.x; i < CFEAT*64; i += 256) {
        int c = i >> 6, o = i & 63;
        Ws[i] = W[o*131 + 3 + c];
    }
    int kbase = blockIdx.x * 32;
    const float* fb = feats + (size_t)b*CFEAT*KKEY + kbase;
    for (int i = threadIdx.x; i < CFEAT*8; i += 256) {
        int c = i >> 3, q = i & 7;
        *(float4*)(fs + c*32 + q*4) = *(const float4*)(fb + (size_t)c*KKEY + q*4);
    }
    __syncthreads();

    int o  = threadIdx.x & 63;
    int kk = threadIdx.x >> 6;
    ull acc0 = 0, acc1 = 0, acc2 = 0, acc3 = 0;
    #pragma unroll 4
    for (int c = 0; c < CFEAT; c++) {
        float w = Ws[c*64 + o];
        ull wd = pack2(w, w);
        const ull* f = (const ull*)(fs + c*32 + kk*8);
        acc0 = ffma2(wd, f[0], acc0);
        acc1 = ffma2(wd, f[1], acc1);
        acc2 = ffma2(wd, f[2], acc2);
        acc3 = ffma2(wd, f[3], acc3);
    }
    size_t base = ((size_t)(sc*2 + b)*KKEY + kbase + kk*8) << 6;
    int oi = ((o & 31) << 1) + (o >> 5);
    float2 u;
    u = unpack2(acc0); g_pre[base + oi] = u.x; g_pre[base + 64 + oi] = u.y;
    u = unpack2(acc1); g_pre[base + 128 + oi] = u.x; g_pre[base + 192 + oi] = u.y;
    u = unpack2(acc2); g_pre[base + 256 + oi] = u.x; g_pre[base + 320 + oi] = u.y;
    u = unpack2(acc3); g_pre[base + 384 + oi] = u.x; g_pre[base + 448 + oi] = u.y;
}

// ---------------- kernel Q: ball query -> padded idx + rel coords ----------
__global__ void __launch_bounds__(256) kQ(const float* __restrict__ kxyzg) {
    __shared__ float kp[KKEY*3];               // interleaved xyz
    __shared__ int idx1s[8][32], idx0s[8][16];

    const int b = blockIdx.x / 1296;
    const float* kb = kxyzg + (size_t)b*KKEY*3;
    for (int i = threadIdx.x; i < KKEY*3; i += 256) kp[i] = kb[i];
    __syncthreads();

    const int w = threadIdx.x >> 5, lane = threadIdx.x & 31;
    const int p = blockIdx.x*8 + w;
    const float px = g_new_xyz[(size_t)p*3], py = g_new_xyz[(size_t)p*3+1],
                pz = g_new_xyz[(size_t)p*3+2];
    const float pn = fmaf(px,px, fmaf(py,py, pz*pz));

    const float R0 = 0.8f*0.8f, R1 = 1.6f*1.6f;
    int* l1 = idx1s[w];
    int* l0 = idx0s[w];
    int c0 = 0, c1 = 0;
    const unsigned lt = (1u << lane) - 1u;
    for (int base = 0; base < KKEY; base += 32) {
        int k = base + lane;
        float kx = kp[3*k], ky = kp[3*k+1], kz = kp[3*k+2];
        float kn  = fmaf(kx,kx, fmaf(ky,ky, kz*kz));
        float dot = fmaf(px,kx, fmaf(py,ky, pz*kz));
        float d2  = fmaf(-2.f, dot, pn + kn);
        bool v1 = d2 < R1, v0 = d2 < R0;
        unsigned m1 = __ballot_sync(0xffffffffu, v1);
        unsigned m0 = __ballot_sync(0xffffffffu, v0);
        if (c1 < 32 && m1) {
            if (v1) { int rk = c1 + __popc(m1 & lt); if (rk < 32) l1[rk] = k; }
            c1 = min(32, c1 + __popc(m1));
        }
        if (c0 < 16 && m0) {
            if (v0) { int rk = c0 + __popc(m0 & lt); if (rk < 16) l0[rk] = k; }
            c0 = min(16, c0 + __popc(m0));
        }
        if (c0 >= 16 && c1 >= 32) break;
    }
    __syncwarp();
    if (c1 == 0) { if (lane == 0) l1[0] = 0; c1 = 1; }
    if (c0 == 0) { if (lane == 0) l0[0] = 0; c0 = 1; }
    __syncwarp();
    {
        int f1 = l1[0], f0 = l0[0];
        if (lane >= c1) l1[lane] = f1;
        if (lane < 16 && lane >= c0) l0[lane] = f0;
    }
    __syncwarp();

    {
        int k = l1[lane];
        g_rel1[(size_t)p*32 + lane] =
            make_float4(kp[3*k]-px, kp[3*k+1]-py, kp[3*k+2]-pz, __int_as_float(k));
        if (lane < 16) {
            int k0 = l0[lane];
            g_rel0[(size_t)p*16 + lane] =
                make_float4(kp[3*k0]-px, kp[3*k0+1]-py, kp[3*k0+2]-pz, __int_as_float(k0));
        }
    }
}

// ---------------- kernel C2: layer0 + tf32 MMA layer1 + maxpool ------------
// 384 threads = 12 warps = 12 points/block; dyn smem words:
//  wpk[2][8kt][8nt][32] uint2            0     .. 8192
//  wxyz[2][3][64]                        8192  .. 8576
//  b0s[128]                              8576  .. 8704
//  b1s[128]                              8704  .. 8832
//  hw[12][16*68]                         8832  .. 21888
#define KC2_SMEM_WORDS 21888
#define OFF2_WXYZ 8192
#define OFF2_B0   8576
#define OFF2_B1   8704
#define OFF2_HW   8832

__global__ void __launch_bounds__(384, 2) kC2(
    const float* __restrict__ w00, const float* __restrict__ b00,
    const float* __restrict__ w01, const float* __restrict__ b01,
    const float* __restrict__ w10, const float* __restrict__ b10,
    const float* __restrict__ w11, const float* __restrict__ b11)
{
    extern __shared__ float sm[];
    uint2*    wpk  = (uint2*)sm;               // [sc][kt][nt][lane]
    float*    wxyz = sm + OFF2_WXYZ;
    float*    b0s  = sm + OFF2_B0;
    float*    b1s  = sm + OFF2_B1;
    unsigned* hwg  = (unsigned*)(sm + OFF2_HW);

    // fill packed b-fragment table: values identical to the R5 wt reads
    for (int i = threadIdx.x; i < 2*8*8*32; i += 384) {
        int lane2 = i & 31, nt = (i >> 5) & 7, kt = (i >> 8) & 7, sc = i >> 11;
        int gid2 = lane2 >> 2, tig2 = lane2 & 3;
        const float* W1 = sc ? w11 : w01;
        int o = nt*8 + gid2, j = kt*8 + tig2;
        wpk[i] = make_uint2(f2tf32(W1[o*64 + j]), f2tf32(W1[o*64 + j + 4]));
    }
    for (int i = threadIdx.x; i < 2*3*64; i += 384) {
        int sc = i / 192, t = i % 192, d = t / 64, o = t % 64;
        wxyz[i] = (sc ? w10 : w00)[o*131 + d];
    }
    if (threadIdx.x < 256) {
        int sc = (threadIdx.x >> 6) & 1, o = threadIdx.x & 63;
        if (threadIdx.x < 128) b0s[threadIdx.x] = (sc ? b10 : b00)[o];
        else                   b1s[threadIdx.x - 128] = (sc ? b11 : b01)[o];
    }
    __syncthreads();

    const int w = threadIdx.x >> 5, lane = threadIdx.x & 31;
    const int gid = lane >> 2, tig = lane & 3;
    const int p  = blockIdx.x*12 + w;
    const int b  = p / NPTS;
    const int rp = p % NPTS;
    const int n  = rp / M_GRID, mm = rp % M_GRID;

    const float4 r1 = g_rel1[(size_t)p*32 + lane];
    float4 r0 = make_float4(0.f,0.f,0.f,0.f);
    if (lane < 16) r0 = g_rel0[(size_t)p*16 + lane];

    unsigned* hw = hwg + w*1088;       // [s 0..15][j], pitch 68

    #pragma unroll
    for (int sc = 0; sc < 2; sc++) {
        const int NPASS = sc ? 2 : 1;
        const float* preb = g_pre + ((size_t)(sc*2 + b)*KKEY << 6);
        const uint2* wps = wpk + sc*2048;
        const float* wx = wxyz + sc*192;
        const float bias0a = b0s[sc*64 + lane],  bias0b = b0s[sc*64 + lane + 32];
        const float wxa0 = wx[lane],    wxa1 = wx[64+lane],  wxa2 = wx[128+lane];
        const float wxb0 = wx[lane+32], wxb1 = wx[96+lane],  wxb2 = wx[160+lane];
        const float4 rr = sc ? r1 : r0;

        float cm0[8], cm1[8];
        #pragma unroll
        for (int nt = 0; nt < 8; nt++) { cm0[nt] = -3.4e38f; cm1[nt] = -3.4e38f; }

        for (int pass = 0; pass < NPASS; pass++) {
            // ---- layer 0: 16 samples -> hw (batched LDG) ----
            #pragma unroll
            for (int s0 = 0; s0 < 16; s0 += 4) {
                float rxs[4], rys[4], rzs[4];
                float2 pr[4];
                #pragma unroll
                for (int s = 0; s < 4; s++) {
                    int si = pass*16 + s0 + s;
                    rxs[s] = __shfl_sync(0xffffffffu, rr.x, si);
                    rys[s] = __shfl_sync(0xffffffffu, rr.y, si);
                    rzs[s] = __shfl_sync(0xffffffffu, rr.z, si);
                    int k = __float_as_int(__shfl_sync(0xffffffffu, rr.w, si));
                    pr[s] = *(const float2*)(preb + ((size_t)k << 6) + (lane << 1));
                }
                #pragma unroll
                for (int s = 0; s < 4; s++) {
                    float va = pr[s].x + bias0a;
                    va = fmaf(rxs[s], wxa0, va);
                    va = fmaf(rys[s], wxa1, va);
                    va = fmaf(rzs[s], wxa2, va);
                    float vb = pr[s].y + bias0b;
                    vb = fmaf(rxs[s], wxb0, vb);
                    vb = fmaf(rys[s], wxb1, vb);
                    vb = fmaf(rzs[s], wxb2, vb);
                    hw[(s0+s)*68 + lane]      = f2tf32(fmaxf(va, 0.f));
                    hw[(s0+s)*68 + 32 + lane] = f2tf32(fmaxf(vb, 0.f));
                }
            }
            __syncwarp();

            // ---- layer 1 MMA over this 16-sample tile ----
            float acc[8][4];
            #pragma unroll
            for (int nt = 0; nt < 8; nt++)
                acc[nt][0] = acc[nt][1] = acc[nt][2] = acc[nt][3] = 0.f;
            #pragma unroll
            for (int kt = 0; kt < 8; kt++) {
                unsigned a[4];
                const unsigned* hrow = hw + gid*68 + kt*8 + tig;
                a[0] = hrow[0];
                a[1] = hrow[8*68];
                a[2] = hrow[4];
                a[3] = hrow[8*68 + 4];
                const uint2* wrow = wps + kt*256 + lane;
                #pragma unroll
                for (int nt = 0; nt < 8; nt++) {
                    uint2 bb = wrow[nt*32];
                    mma_tf32(acc[nt], a, bb.x, bb.y);
                }
            }
            #pragma unroll
            for (int nt = 0; nt < 8; nt++) {
                cm0[nt] = fmaxf(cm0[nt], fmaxf(acc[nt][0], acc[nt][2]));
                cm1[nt] = fmaxf(cm1[nt], fmaxf(acc[nt][1], acc[nt][3]));
            }
            __syncwarp();
        }

        // reduce across row-groups (lane bits 2..4)
        #pragma unroll
        for (int off = 4; off <= 16; off <<= 1) {
            #pragma unroll
            for (int nt = 0; nt < 8; nt++) {
                cm0[nt] = fmaxf(cm0[nt], __shfl_xor_sync(0xffffffffu, cm0[nt], off));
                cm1[nt] = fmaxf(cm1[nt], __shfl_xor_sync(0xffffffffu, cm1[nt], off));
            }
        }
        size_t rowb = (size_t)(b*NPROP + n)*QDIM + (size_t)sc*64*M_GRID + mm;
        if (gid == 0) {
            #pragma unroll
            for (int nt = 0; nt < 8; nt++) {
                int o0 = nt*8 + tig*2;
                float v0 = fmaxf(cm0[nt] + b1s[sc*64 + o0],     0.f);
                float v1 = fmaxf(cm1[nt] + b1s[sc*64 + o0 + 1], 0.f);
                g_pooled[rowb + (size_t)o0*M_GRID]     = v0;
                g_pooled[rowb + (size_t)(o0+1)*M_GRID] = v1;
            }
        }
    }
}

// ---------------- kernel D: K-split GEMM, 4x8 thread tile -------------------
#define KD_KT 16
#define XSP 36
#define WSP 260
__global__ void __launch_bounds__(256) kD(const float* __restrict__ w0) {
    __shared__ float xs[2][KD_KT*XSP];
    __shared__ float ws[2][KD_KT*WSP];
    const int tid = threadIdx.x;
    const int tx = tid & 31, ty = tid >> 5;
    const int rowbase = blockIdx.y * 32;
    const int kg0 = blockIdx.z * KCHUNK;

    const int xrow = tid >> 3, xk = (tid & 7) << 1;
    const int wcol = tid >> 2, wk = (tid & 3) << 2;

    const float* xg = g_pooled + (size_t)(rowbase + xrow)*QDIM + kg0 + xk;
    const float* wg0 = w0 + (size_t)(wcol      )*QDIM + kg0 + wk;
    const float* wg1 = w0 + (size_t)(wcol +  64)*QDIM + kg0 + wk;
    const float* wg2 = w0 + (size_t)(wcol + 128)*QDIM + kg0 + wk;
    const float* wg3 = w0 + (size_t)(wcol + 192)*QDIM + kg0 + wk;

    float2 xv = *(const float2*)xg;
    float4 wv0 = *(const float4*)wg0;
    float4 wv1 = *(const float4*)wg1;
    float4 wv2 = *(const float4*)wg2;
    float4 wv3 = *(const float4*)wg3;

    float acc[4][8] = {};
    const int NT = KCHUNK / KD_KT;      // 16
    for (int t = 0; t < NT; t++) {
        float* xsc = xs[t & 1];
        float* wsc = ws[t & 1];
        xsc[(xk  )*XSP + xrow] = xv.x;
        xsc[(xk+1)*XSP + xrow] = xv.y;
        #pragma unroll
        for (int j = 0; j < 4; j++) {
            wsc[(wk+j)*WSP + wcol      ] = ((const float*)&wv0)[j];
            wsc[(wk+j)*WSP + wcol +  64] = ((const float*)&wv1)[j];
            wsc[(wk+j)*WSP + wcol + 128] = ((const float*)&wv2)[j];
            wsc[(wk+j)*WSP + wcol + 192] = ((const float*)&wv3)[j];
        }
        __syncthreads();
        if (t + 1 < NT) {
            int d = (t + 1) * KD_KT;
            xv  = *(const float2*)(xg + d);
            wv0 = *(const float4*)(wg0 + d);
            wv1 = *(const float4*)(wg1 + d);
            wv2 = *(const float4*)(wg2 + d);
            wv3 = *(const float4*)(wg3 + d);
        }
        #pragma unroll
        for (int kk = 0; kk < KD_KT; kk++) {
            float4 xq = *(const float4*)(xsc + kk*XSP + ty*4);
            float4 wa = *(const float4*)(wsc + kk*WSP + tx*4);
            float4 wb = *(const float4*)(wsc + kk*WSP + 128 + tx*4);
            const float xr[4] = {xq.x, xq.y, xq.z, xq.w};
            const float wc[8] = {wa.x, wa.y, wa.z, wa.w, wb.x, wb.y, wb.z, wb.w};
            #pragma unroll
            for (int i = 0; i < 4; i++)
                #pragma unroll
                for (int j = 0; j < 8; j++)
                    acc[i][j] = fmaf(xr[i], wc[j], acc[i][j]);
        }
        __syncthreads();
    }
    #pragma unroll
    for (int i = 0; i < 4; i++) {
        int row = rowbase + ty*4 + i;
        float* pp = g_partial + ((size_t)blockIdx.z*96 + row)*256;
        *(float4*)(pp + tx*4)       = make_float4(acc[i][0], acc[i][1], acc[i][2], acc[i][3]);
        *(float4*)(pp + 128 + tx*4) = make_float4(acc[i][4], acc[i][5], acc[i][6], acc[i][7]);
    }
}

// ---------------- kernel E: reduce + relu + 256x256 GEMM + relu ------------
__global__ void __launch_bounds__(256) kE(const float* __restrict__ rb0,
                                          const float* __restrict__ rw1,
                                          const float* __restrict__ rb1,
                                          float* __restrict__ out) {
    __shared__ float h2s[256];
    __shared__ float w1s[256*33];
    const int row = blockIdx.x;
    const int o = threadIdx.x;
    float s = rb0[o];
    #pragma unroll 4
    for (int ks = 0; ks < KSPLIT; ks++)
        s += g_partial[((size_t)ks*96 + row)*256 + o];
    h2s[o] = fmaxf(s, 0.f);
    __syncthreads();

    float acc = rb1[o];
    for (int jt = 0; jt < 256; jt += 32) {
        for (int i = threadIdx.x; i < 8192; i += 256) {
            int oo = i >> 5, jj = i & 31;
            w1s[oo*33 + jj] = rw1[(size_t)oo*256 + jt + jj];
        }
        __syncthreads();
        #pragma unroll
        for (int jj = 0; jj < 32; jj++)
            acc = fmaf(h2s[jt + jj], w1s[o*33 + jj], acc);
        __syncthreads();
    }
    out[(size_t)row*256 + o] = fmaxf(acc, 0.f);
}

// ---------------- launch ----------------
extern "C" void kernel_launch(void* const* d_in, const int* in_sizes, int n_in,
                              void* d_out, int out_size) {
    const float* proposals = (const float*)d_in[0];
    const float* kxyz      = (const float*)d_in[1];
    const float* kfeat     = (const float*)d_in[2];
    const float* gnoise    = (const float*)d_in[3];
    const float* w00 = (const float*)d_in[4];
    const float* b00 = (const float*)d_in[5];
    const float* w01 = (const float*)d_in[6];
    const float* b01 = (const float*)d_in[7];
    const float* w10 = (const float*)d_in[8];
    const float* b10 = (const float*)d_in[9];
    const float* w11 = (const float*)d_in[10];
    const float* b11 = (const float*)d_in[11];
    const float* rw0 = (const float*)d_in[12];
    const float* rb0 = (const float*)d_in[13];
    const float* rw1 = (const float*)d_in[14];
    const float* rb1 = (const float*)d_in[15];
    float* out = (float*)d_out;

    cudaFuncSetAttribute(kC2, cudaFuncAttributeMaxDynamicSharedMemorySize,
                         KC2_SMEM_WORDS * 4);

    kA<<<(NTOT + 255)/256, 256>>>(proposals, gnoise);
    kB<<<dim3(KKEY/32, 4), 256>>>(kfeat, w00, w10);
    kQ<<<NTOT/8, 256>>>(kxyz);
    kC2<<<NTOT/12, 384, KC2_SMEM_WORDS * 4>>>(w00, b00, w01, b01,
                                              w10, b10, w11, b11);
    kD<<<dim3(1, 96/32, KSPLIT), 256>>>(rw0);
    kE<<<96, 256>>>(rb0, rw1, rb1, out);
}